// round 14
// baseline (speedup 1.0000x reference)
#include <cuda_runtime.h>
#include <math.h>
#include <stdint.h>
#include <mma.h>

using namespace nvcuda;

// ---------------------------------------------------------------------------
// Problem constants
// ---------------------------------------------------------------------------
#define DIM   768
#define NHEAD 12
#define HD    64
#define BATCH 8
#define SEQ   1024
#define TOK   (BATCH*SEQ)
#define HID   3072
#define S1V   320
#define S2V   384
#define EPS   1e-5f
#define SCALE 0.125f

// ---------------------------------------------------------------------------
// Scratch
// ---------------------------------------------------------------------------
__device__ float g_normx[TOK * DIM];
__device__ float g_qkv  [TOK * 3 * DIM];
__device__ float g_y    [TOK * DIM];
__device__ float g_h    [TOK * HID];
__device__ float g_wq[3 * DIM * DIM];
__device__ float g_wp[DIM * DIM];
__device__ float g_w1[HID * DIM];
__device__ float g_w2[DIM * HID];

// ---------------------------------------------------------------------------
// Fused weight rounding
// ---------------------------------------------------------------------------
#define NQ4 (3 * DIM * DIM / 4)
#define NP4 (DIM * DIM / 4)
#define N14 (HID * DIM / 4)
#define N24 (DIM * HID / 4)
#define NTOT4 (NQ4 + NP4 + N14 + N24)

__global__ void __launch_bounds__(256) round_all_kernel(
    const float* __restrict__ sq, float* __restrict__ dq,
    const float* __restrict__ sp, float* __restrict__ dp,
    const float* __restrict__ s1, float* __restrict__ d1,
    const float* __restrict__ s2, float* __restrict__ d2)
{
    int i = blockIdx.x * 256 + threadIdx.x;
    if (i >= NTOT4) return;
    const float4* src;
    float4* dst;
    int off;
    if (i < NQ4)                  { src = (const float4*)sq; dst = (float4*)dq; off = i; }
    else if (i < NQ4 + NP4)       { src = (const float4*)sp; dst = (float4*)dp; off = i - NQ4; }
    else if (i < NQ4 + NP4 + N14) { src = (const float4*)s1; dst = (float4*)d1; off = i - NQ4 - NP4; }
    else                          { src = (const float4*)s2; dst = (float4*)d2; off = i - NQ4 - NP4 - N14; }
    float4 v = src[off];
    v.x = wmma::__float_to_tf32(v.x);
    v.y = wmma::__float_to_tf32(v.y);
    v.z = wmma::__float_to_tf32(v.z);
    v.w = wmma::__float_to_tf32(v.w);
    dst[off] = v;
}

// ---------------------------------------------------------------------------
// PTX helpers
// ---------------------------------------------------------------------------
__device__ __forceinline__ void cp_async16(uint32_t dst, const float* src) {
    asm volatile("cp.async.cg.shared.global [%0], [%1], 16;\n"
                 :: "r"(dst), "l"(src));
}
__device__ __forceinline__ void cp_commit() {
    asm volatile("cp.async.commit_group;\n" ::: "memory");
}
__device__ __forceinline__ void cp_wait1() {
    asm volatile("cp.async.wait_group 1;\n" ::: "memory");
}
__device__ __forceinline__ void ldsm4(uint32_t& r0, uint32_t& r1,
                                      uint32_t& r2, uint32_t& r3, uint32_t addr) {
    asm volatile("ldmatrix.sync.aligned.m8n8.x4.shared.b16 {%0,%1,%2,%3}, [%4];"
                 : "=r"(r0), "=r"(r1), "=r"(r2), "=r"(r3) : "r"(addr));
}
__device__ __forceinline__ void mma8(float* d,
    uint32_t a0, uint32_t a1, uint32_t a2, uint32_t a3,
    uint32_t b0, uint32_t b1)
{
    asm volatile(
        "mma.sync.aligned.m16n8k8.row.col.f32.tf32.tf32.f32 "
        "{%0,%1,%2,%3},{%4,%5,%6,%7},{%8,%9},{%0,%1,%2,%3};"
        : "+f"(d[0]), "+f"(d[1]), "+f"(d[2]), "+f"(d[3])
        : "r"(a0), "r"(a1), "r"(a2), "r"(a3), "r"(b0), "r"(b1));
}

// ---------------------------------------------------------------------------
// Raw-mma TF32 NT GEMM (proven R9/R12 config — unchanged).
// ---------------------------------------------------------------------------
#define LDA 36
#define STAGE_F (128 * LDA)
#define GEMM_SMEM (3 * 2 * STAGE_F * 4)

template<int EPI>
__global__ void __launch_bounds__(128, 2) gemm_mma(
    const float* __restrict__ A, const float* __restrict__ B,
    const float* __restrict__ bias, const float* __restrict__ res,
    float* __restrict__ C, int M, int N, int K)
{
    extern __shared__ float smem[];

    const int tid  = threadIdx.x;
    const int w    = tid >> 5;
    const int lane = tid & 31;
    const int bm = blockIdx.y, bn = blockIdx.x;
    const int wm = w & 1;
    const int wn = w >> 1;

    const float* Abase = A + (size_t)(bm * 128) * K;
    const float* Bbase = B + (size_t)(bn * 128) * K;

    const uint32_t smem_u32 = (uint32_t)__cvta_generic_to_shared(smem);

    const int arow_l = lane & 15;
    const int acol_l = (lane >> 4) << 2;
    const int brow_l = (lane & 7) + ((lane >> 4) << 3);
    const int bcol_l = ((lane >> 3) & 1) << 2;

    float acc[4][8][4];
#pragma unroll
    for (int i = 0; i < 4; i++)
#pragma unroll
        for (int j = 0; j < 8; j++)
#pragma unroll
            for (int e = 0; e < 4; e++) acc[i][j][e] = 0.f;

    const int KC = K >> 5;

    auto issue = [&](int c, int s) {
        const int k0 = c << 5;
        const uint32_t sbase = smem_u32 + (uint32_t)(s * 2 * STAGE_F) * 4u;
#pragma unroll
        for (int i = 0; i < 8; i++) {
            int idx = tid + i * 128, r = idx >> 3, cc = idx & 7;
            cp_async16(sbase + (uint32_t)(r * LDA + cc * 4) * 4u,
                       Abase + (size_t)r * K + k0 + cc * 4);
        }
#pragma unroll
        for (int i = 0; i < 8; i++) {
            int idx = tid + i * 128, r = idx >> 3, cc = idx & 7;
            cp_async16(sbase + (uint32_t)(STAGE_F + r * LDA + cc * 4) * 4u,
                       Bbase + (size_t)r * K + k0 + cc * 4);
        }
    };

    issue(0, 0); cp_commit();
    issue(1, 1); cp_commit();

    int s3 = 2;
    for (int c = 0; c < KC; c++) {
        cp_wait1();
        __syncthreads();
        if (c + 2 < KC) issue(c + 2, s3);
        cp_commit();
        s3 = (s3 == 2) ? 0 : s3 + 1;

        const uint32_t soff = (uint32_t)((c % 3) * 2 * STAGE_F) * 4u;
        const uint32_t abase = smem_u32 + soff +
            (uint32_t)((wm * 64 + arow_l) * LDA + acol_l) * 4u;
        const uint32_t bbase = smem_u32 + soff + (uint32_t)STAGE_F * 4u +
            (uint32_t)((wn * 64 + brow_l) * LDA + bcol_l) * 4u;

#pragma unroll
        for (int kk = 0; kk < 32; kk += 8) {
            uint32_t a[4][4], b[4][4];
#pragma unroll
            for (int i = 0; i < 4; i++)
                ldsm4(a[i][0], a[i][1], a[i][2], a[i][3],
                      abase + (uint32_t)(i * 16 * LDA + kk) * 4u);
#pragma unroll
            for (int j = 0; j < 4; j++)
                ldsm4(b[j][0], b[j][1], b[j][2], b[j][3],
                      bbase + (uint32_t)(j * 16 * LDA + kk) * 4u);
#pragma unroll
            for (int i = 0; i < 4; i++)
#pragma unroll
                for (int j = 0; j < 4; j++) {
                    mma8(acc[i][2 * j],     a[i][0], a[i][1], a[i][2], a[i][3],
                         b[j][0], b[j][1]);
                    mma8(acc[i][2 * j + 1], a[i][0], a[i][1], a[i][2], a[i][3],
                         b[j][2], b[j][3]);
                }
        }
    }

    // direct-to-global epilogue
    const int gr0 = bm * 128 + wm * 64 + (lane >> 2);
    const int gc0 = bn * 128 + wn * 64 + 2 * (lane & 3);

#pragma unroll
    for (int i = 0; i < 4; i++) {
        const int r0 = gr0 + i * 16;
        const int r1 = r0 + 8;
#pragma unroll
        for (int jj = 0; jj < 8; jj++) {
            const int col = gc0 + jj * 8;
            float* d = acc[i][jj];
            float v0 = d[0], v1 = d[1], v2 = d[2], v3 = d[3];
            if (EPI == 1) {
                float b0 = bias[col], b1 = bias[col + 1];
                const float* rr0 = res + (size_t)r0 * N + col;
                const float* rr1 = res + (size_t)r1 * N + col;
                v0 += b0 + rr0[0]; v1 += b1 + rr0[1];
                v2 += b0 + rr1[0]; v3 += b1 + rr1[1];
            } else if (EPI == 2) {
                float b0 = bias[col], b1 = bias[col + 1];
                v0 += b0; v1 += b1; v2 += b0; v3 += b1;
                v0 = wmma::__float_to_tf32(0.5f * v0 * (1.0f + erff(v0 * 0.70710678118654752f)));
                v1 = wmma::__float_to_tf32(0.5f * v1 * (1.0f + erff(v1 * 0.70710678118654752f)));
                v2 = wmma::__float_to_tf32(0.5f * v2 * (1.0f + erff(v2 * 0.70710678118654752f)));
                v3 = wmma::__float_to_tf32(0.5f * v3 * (1.0f + erff(v3 * 0.70710678118654752f)));
            }
            *(float2*)(C + (size_t)r0 * N + col) = make_float2(v0, v1);
            *(float2*)(C + (size_t)r1 * N + col) = make_float2(v2, v3);
        }
    }
}

// ---------------------------------------------------------------------------
// Split LayerNorm (unchanged)
// ---------------------------------------------------------------------------
__global__ void __launch_bounds__(128) ln_split_kernel(
    const float* __restrict__ x,
    const float* __restrict__ ga, const float* __restrict__ ba,
    const float* __restrict__ gb, const float* __restrict__ bb,
    const float* __restrict__ gc, const float* __restrict__ bc,
    float* __restrict__ out)
{
    __shared__ float xs[DIM];
    __shared__ float st_m[3];
    __shared__ float st_r[3];

    const int row = blockIdx.x;
    const int tid = threadIdx.x;
    const int w = tid >> 5, lane = tid & 31;

    const float4* xr4 = (const float4*)(x + (size_t)row * DIM);
    float4* xs4 = (float4*)xs;
    xs4[tid] = xr4[tid];
    if (tid < 64) xs4[128 + tid] = xr4[128 + tid];
    __syncthreads();

    if (w < 3) {
        const int lo  = (w == 0) ? 0 : ((w == 1) ? S1V : S2V);
        const int hi  = (w == 0) ? S1V : ((w == 1) ? S2V : DIM);
        float s1 = 0.f, s2 = 0.f;
        for (int i = lo + lane; i < hi; i += 32) {
            float v = xs[i];
            s1 += v; s2 += v * v;
        }
#pragma unroll
        for (int off = 16; off > 0; off >>= 1) {
            s1 += __shfl_xor_sync(0xffffffffu, s1, off);
            s2 += __shfl_xor_sync(0xffffffffu, s2, off);
        }
        if (lane == 0) {
            float len = (float)(hi - lo);
            float m = s1 / len;
            float var = s2 / len - m * m;
            st_m[w] = m;
            st_r[w] = rsqrtf(var + EPS);
        }
    }
    __syncthreads();

    float* orow = out + (size_t)row * DIM;
    for (int i = tid; i < DIM; i += 128) {
        int s = (i < S1V) ? 0 : ((i < S2V) ? 1 : 2);
        int li = i - ((s == 0) ? 0 : ((s == 1) ? S1V : S2V));
        const float* g  = (s == 0) ? ga : ((s == 1) ? gb : gc);
        const float* be = (s == 0) ? ba : ((s == 1) ? bb : bc);
        float v = (xs[i] - st_m[s]) * st_r[s] * g[li] + be[li];
        orow[i] = wmma::__float_to_tf32(v);
    }
}

// ---------------------------------------------------------------------------
// Tensor-core flash attention v3:
// 256 threads (8 warps), 128 q-rows per block, 64-key tiles.
// Q fragments hoisted to registers (loop-invariant). P lives in the freed
// 128-row Q region (each warp's Q rows == its P rows: no cross-warp hazard,
// and the K tile is never overwritten -> one fewer barrier per tile).
// smem: qp[128][68] (Q then P), ks[64][68], vs[64][72]
// ---------------------------------------------------------------------------
#define ALDK 68
#define ALDV 72
#define ATTN_SMEM ((128 * ALDK + 64 * ALDK + 64 * ALDV) * 4)

__global__ void __launch_bounds__(256) attn_kernel(
    const float* __restrict__ qkv, float* __restrict__ y)
{
    extern __shared__ float sm[];
    float* qp = sm;                       // 128 x 68 : Q (prologue) then P
    float* ks = sm + 128 * ALDK;          // 64 x 68
    float* vs = sm + (128 + 64) * ALDK;   // 64 x 72

    const int tid  = threadIdx.x;
    const int w    = tid >> 5;
    const int lane = tid & 31;
    const int qr   = lane >> 2;
    const int qc   = lane & 3;
    const int n0 = blockIdx.x * 128;
    const int b = blockIdx.y / NHEAD;
    const int h = blockIdx.y % NHEAD;

    const uint32_t sm_u32 = (uint32_t)__cvta_generic_to_shared(sm);
    const uint32_t qp_u32 = sm_u32;
    const uint32_t ks_u32 = sm_u32 + 128 * ALDK * 4;

    const int arow_l = lane & 15;
    const int acol_l = (lane >> 4) << 2;
    const int brow_l = (lane & 7) + ((lane >> 4) << 3);
    const int bcol_l = ((lane >> 3) & 1) << 2;

    const float* base = qkv + (size_t)b * SEQ * (3 * DIM) + h * HD;

    // ---- prologue: Q -> smem, then hoist fragments into registers
    for (int i = tid; i < 128 * 16; i += 256) {
        int r = i >> 4, c4 = (i & 15) * 4;
        *(float4*)(qp + r * ALDK + c4) =
            *(const float4*)(base + (size_t)(n0 + r) * (3 * DIM) + c4);
    }
    __syncthreads();

    uint32_t qa[8][4];
    {
        const uint32_t qa_base = qp_u32 +
            (uint32_t)((w * 16 + arow_l) * ALDK + acol_l) * 4u;
#pragma unroll
        for (int k8 = 0; k8 < 8; k8++)
            ldsm4(qa[k8][0], qa[k8][1], qa[k8][2], qa[k8][3],
                  qa_base + (uint32_t)(k8 * 8) * 4u);
    }
    // No barrier needed: each warp's P writes target only its own Q rows.

    float o[8][4];
    float m0 = -INFINITY, m1 = -INFINITY, l0 = 0.f, l1 = 0.f;
#pragma unroll
    for (int j = 0; j < 8; j++)
#pragma unroll
        for (int e = 0; e < 4; e++) o[j][e] = 0.f;

    const int rowA = (w * 16 + qr) * ALDK;    // P row base (in qp)
    const int rowB = rowA + 8 * ALDK;
    const uint32_t pa_base = qp_u32 +
        (uint32_t)((w * 16 + arow_l) * ALDK + acol_l) * 4u;

    for (int kt = 0; kt < SEQ / 64; kt++) {
        // load K, V tiles (64 rows x 16 float4 each, 256 threads)
        for (int i = tid; i < 64 * 16; i += 256) {
            int r = i >> 4, c4 = (i & 15) * 4;
            const float* kp = base + DIM + (size_t)(kt * 64 + r) * (3 * DIM) + c4;
            *(float4*)(ks + r * ALDK + c4) = *(const float4*)kp;
            *(float4*)(vs + r * ALDV + c4) = *(const float4*)(kp + DIM);
        }
        __syncthreads();

        // ---- S = Q @ K^T (Q from registers, K via ldsm)
        float s[8][4];
#pragma unroll
        for (int j = 0; j < 8; j++)
#pragma unroll
            for (int e = 0; e < 4; e++) s[j][e] = 0.f;

#pragma unroll
        for (int k8 = 0; k8 < 8; k8++) {
            const int kb = k8 * 8;
#pragma unroll
            for (int q = 0; q < 4; q++) {
                uint32_t b0, b1, b2, b3;
                ldsm4(b0, b1, b2, b3, ks_u32 +
                      (uint32_t)((16 * q + brow_l) * ALDK + kb + bcol_l) * 4u);
                mma8(s[2 * q],     qa[k8][0], qa[k8][1], qa[k8][2], qa[k8][3], b0, b1);
                mma8(s[2 * q + 1], qa[k8][0], qa[k8][1], qa[k8][2], qa[k8][3], b2, b3);
            }
        }
        // (no barrier: P goes to qp, K tile stays intact)

        // ---- online softmax
        float mx0 = -INFINITY, mx1 = -INFINITY;
#pragma unroll
        for (int j = 0; j < 8; j++) {
#pragma unroll
            for (int e = 0; e < 4; e++) s[j][e] *= SCALE;
            mx0 = fmaxf(mx0, fmaxf(s[j][0], s[j][1]));
            mx1 = fmaxf(mx1, fmaxf(s[j][2], s[j][3]));
        }
        mx0 = fmaxf(mx0, __shfl_xor_sync(0xffffffffu, mx0, 1));
        mx0 = fmaxf(mx0, __shfl_xor_sync(0xffffffffu, mx0, 2));
        mx1 = fmaxf(mx1, __shfl_xor_sync(0xffffffffu, mx1, 1));
        mx1 = fmaxf(mx1, __shfl_xor_sync(0xffffffffu, mx1, 2));

        float mn0 = fmaxf(m0, mx0), mn1 = fmaxf(m1, mx1);
        float c0 = __expf(m0 - mn0), c1 = __expf(m1 - mn1);
        float rs0 = 0.f, rs1 = 0.f;

#pragma unroll
        for (int j = 0; j < 8; j++) {
            float p0 = __expf(s[j][0] - mn0);
            float p1 = __expf(s[j][1] - mn0);
            float p2 = __expf(s[j][2] - mn1);
            float p3 = __expf(s[j][3] - mn1);
            rs0 += p0 + p1; rs1 += p2 + p3;
            float* pr0 = qp + rowA + j * 8 + qc * 2;
            float* pr1 = qp + rowB + j * 8 + qc * 2;
            pr0[0] = p0; pr0[1] = p1;
            pr1[0] = p2; pr1[1] = p3;
            o[j][0] *= c0; o[j][1] *= c0; o[j][2] *= c1; o[j][3] *= c1;
        }
        rs0 += __shfl_xor_sync(0xffffffffu, rs0, 1);
        rs0 += __shfl_xor_sync(0xffffffffu, rs0, 2);
        rs1 += __shfl_xor_sync(0xffffffffu, rs1, 1);
        rs1 += __shfl_xor_sync(0xffffffffu, rs1, 2);
        l0 = l0 * c0 + rs0; l1 = l1 * c1 + rs1;
        m0 = mn0; m1 = mn1;
        __syncwarp();      // own P rows visible before ldsm reads them

        // ---- O += P @ V : ldsm for A (P), scalar loads for B (V)
#pragma unroll
        for (int k8 = 0; k8 < 8; k8++) {
            const int kb = k8 * 8;
            uint32_t a0, a1, a2, a3;
            ldsm4(a0, a1, a2, a3, pa_base + (uint32_t)kb * 4u);
#pragma unroll
            for (int j = 0; j < 8; j++) {
                uint32_t b0 = __float_as_uint(vs[(kb + qc) * ALDV + j * 8 + qr]);
                uint32_t b1 = __float_as_uint(vs[(kb + qc + 4) * ALDV + j * 8 + qr]);
                mma8(o[j], a0, a1, a2, a3, b0, b1);
            }
        }
        __syncthreads();   // all warps done with ks/vs before next tile load
    }

    const float i0 = 1.0f / l0, i1 = 1.0f / l1;
    const int gr0 = b * SEQ + n0 + w * 16 + qr;
    float* y0 = y + (size_t)gr0 * DIM + h * HD;
    float* y1 = y0 + (size_t)8 * DIM;
#pragma unroll
    for (int j = 0; j < 8; j++) {
        const int cb = j * 8 + qc * 2;
        y0[cb]     = wmma::__float_to_tf32(o[j][0] * i0);
        y0[cb + 1] = wmma::__float_to_tf32(o[j][1] * i0);
        y1[cb]     = wmma::__float_to_tf32(o[j][2] * i1);
        y1[cb + 1] = wmma::__float_to_tf32(o[j][3] * i1);
    }
}

// ---------------------------------------------------------------------------
// Launch
// ---------------------------------------------------------------------------
extern "C" void kernel_launch(void* const* d_in, const int* in_sizes, int n_in,
                              void* d_out, int out_size)
{
    const float* x      = (const float*)d_in[0];
    const float* ln1a_g = (const float*)d_in[1];
    const float* ln1a_b = (const float*)d_in[2];
    const float* ln1b_g = (const float*)d_in[3];
    const float* ln1b_b = (const float*)d_in[4];
    const float* ln1c_g = (const float*)d_in[5];
    const float* ln1c_b = (const float*)d_in[6];
    const float* ln2a_g = (const float*)d_in[7];
    const float* ln2a_b = (const float*)d_in[8];
    const float* ln2b_g = (const float*)d_in[9];
    const float* ln2b_b = (const float*)d_in[10];
    const float* ln2c_g = (const float*)d_in[11];
    const float* ln2c_b = (const float*)d_in[12];
    const float* qkv_w  = (const float*)d_in[13];
    const float* proj_w = (const float*)d_in[14];
    const float* proj_b = (const float*)d_in[15];
    const float* fc1_w  = (const float*)d_in[16];
    const float* fc1_b  = (const float*)d_in[17];
    const float* fc2_w  = (const float*)d_in[18];
    const float* fc2_b  = (const float*)d_in[19];
    float* out = (float*)d_out;

    float *p_normx, *p_qkv, *p_y, *p_h, *p_wq, *p_wp, *p_w1, *p_w2;
    cudaGetSymbolAddress((void**)&p_normx, g_normx);
    cudaGetSymbolAddress((void**)&p_qkv,   g_qkv);
    cudaGetSymbolAddress((void**)&p_y,     g_y);
    cudaGetSymbolAddress((void**)&p_h,     g_h);
    cudaGetSymbolAddress((void**)&p_wq,    g_wq);
    cudaGetSymbolAddress((void**)&p_wp,    g_wp);
    cudaGetSymbolAddress((void**)&p_w1,    g_w1);
    cudaGetSymbolAddress((void**)&p_w2,    g_w2);

    cudaFuncSetAttribute(attn_kernel,
                         cudaFuncAttributeMaxDynamicSharedMemorySize, ATTN_SMEM);
    cudaFuncSetAttribute(gemm_mma<0>,
                         cudaFuncAttributeMaxDynamicSharedMemorySize, GEMM_SMEM);
    cudaFuncSetAttribute(gemm_mma<1>,
                         cudaFuncAttributeMaxDynamicSharedMemorySize, GEMM_SMEM);
    cudaFuncSetAttribute(gemm_mma<2>,
                         cudaFuncAttributeMaxDynamicSharedMemorySize, GEMM_SMEM);

    // 0. round all weights to tf32 (RN) in one launch
    round_all_kernel<<<(NTOT4 + 255) / 256, 256>>>(
        qkv_w, p_wq, proj_w, p_wp, fc1_w, p_w1, fc2_w, p_w2);

    // 1. norm1
    ln_split_kernel<<<TOK, 128>>>(x, ln1a_g, ln1a_b, ln1b_g, ln1b_b,
                                  ln1c_g, ln1c_b, p_normx);

    // 2. QKV
    gemm_mma<0><<<dim3(3 * DIM / 128, TOK / 128), 128, GEMM_SMEM>>>(
        p_normx, p_wq, nullptr, nullptr, p_qkv, TOK, 3 * DIM, DIM);

    // 3. attention (128 q-rows per block)
    attn_kernel<<<dim3(SEQ / 128, BATCH * NHEAD), 256, ATTN_SMEM>>>(p_qkv, p_y);

    // 4. proj + bias + residual(x)
    gemm_mma<1><<<dim3(DIM / 128, TOK / 128), 128, GEMM_SMEM>>>(
        p_y, p_wp, proj_b, x, out, TOK, DIM, DIM);

    // 5. norm2
    ln_split_kernel<<<TOK, 128>>>(out, ln2a_g, ln2a_b, ln2b_g, ln2b_b,
                                  ln2c_g, ln2c_b, p_normx);

    // 6. FC1 + bias + GELU
    gemm_mma<2><<<dim3(HID / 128, TOK / 128), 128, GEMM_SMEM>>>(
        p_normx, p_w1, fc1_b, nullptr, p_h, TOK, HID, DIM);

    // 7. FC2 + bias + residual(out)
    gemm_mma<1><<<dim3(DIM / 128, TOK / 128), 128, GEMM_SMEM>>>(
        p_h, p_w2, fc2_b, out, out, TOK, DIM, HID);
}

// round 15
// speedup vs baseline: 1.0232x; 1.0232x over previous
#include <cuda_runtime.h>
#include <math.h>
#include <stdint.h>
#include <mma.h>

using namespace nvcuda;

// ---------------------------------------------------------------------------
// Problem constants
// ---------------------------------------------------------------------------
#define DIM   768
#define NHEAD 12
#define HD    64
#define BATCH 8
#define SEQ   1024
#define TOK   (BATCH*SEQ)
#define HID   3072
#define S1V   320
#define S2V   384
#define EPS   1e-5f
#define SCALE 0.125f

// ---------------------------------------------------------------------------
// Scratch
// ---------------------------------------------------------------------------
__device__ float g_normx[TOK * DIM];
__device__ float g_qkv  [TOK * 3 * DIM];
__device__ float g_y    [TOK * DIM];
__device__ float g_h    [TOK * HID];
__device__ float g_wq[3 * DIM * DIM];
__device__ float g_wp[DIM * DIM];
__device__ float g_w1[HID * DIM];
__device__ float g_w2[DIM * HID];

// ---------------------------------------------------------------------------
// Fused weight rounding
// ---------------------------------------------------------------------------
#define NQ4 (3 * DIM * DIM / 4)
#define NP4 (DIM * DIM / 4)
#define N14 (HID * DIM / 4)
#define N24 (DIM * HID / 4)
#define NTOT4 (NQ4 + NP4 + N14 + N24)

__global__ void __launch_bounds__(256) round_all_kernel(
    const float* __restrict__ sq, float* __restrict__ dq,
    const float* __restrict__ sp, float* __restrict__ dp,
    const float* __restrict__ s1, float* __restrict__ d1,
    const float* __restrict__ s2, float* __restrict__ d2)
{
    int i = blockIdx.x * 256 + threadIdx.x;
    if (i >= NTOT4) return;
    const float4* src;
    float4* dst;
    int off;
    if (i < NQ4)                  { src = (const float4*)sq; dst = (float4*)dq; off = i; }
    else if (i < NQ4 + NP4)       { src = (const float4*)sp; dst = (float4*)dp; off = i - NQ4; }
    else if (i < NQ4 + NP4 + N14) { src = (const float4*)s1; dst = (float4*)d1; off = i - NQ4 - NP4; }
    else                          { src = (const float4*)s2; dst = (float4*)d2; off = i - NQ4 - NP4 - N14; }
    float4 v = src[off];
    v.x = wmma::__float_to_tf32(v.x);
    v.y = wmma::__float_to_tf32(v.y);
    v.z = wmma::__float_to_tf32(v.z);
    v.w = wmma::__float_to_tf32(v.w);
    dst[off] = v;
}

// ---------------------------------------------------------------------------
// PTX helpers
// ---------------------------------------------------------------------------
__device__ __forceinline__ void cp_async16(uint32_t dst, const float* src) {
    asm volatile("cp.async.cg.shared.global [%0], [%1], 16;\n"
                 :: "r"(dst), "l"(src));
}
__device__ __forceinline__ void cp_commit() {
    asm volatile("cp.async.commit_group;\n" ::: "memory");
}
__device__ __forceinline__ void cp_wait1() {
    asm volatile("cp.async.wait_group 1;\n" ::: "memory");
}
__device__ __forceinline__ void ldsm4(uint32_t& r0, uint32_t& r1,
                                      uint32_t& r2, uint32_t& r3, uint32_t addr) {
    asm volatile("ldmatrix.sync.aligned.m8n8.x4.shared.b16 {%0,%1,%2,%3}, [%4];"
                 : "=r"(r0), "=r"(r1), "=r"(r2), "=r"(r3) : "r"(addr));
}
__device__ __forceinline__ void mma8(float* d,
    uint32_t a0, uint32_t a1, uint32_t a2, uint32_t a3,
    uint32_t b0, uint32_t b1)
{
    asm volatile(
        "mma.sync.aligned.m16n8k8.row.col.f32.tf32.tf32.f32 "
        "{%0,%1,%2,%3},{%4,%5,%6,%7},{%8,%9},{%0,%1,%2,%3};"
        : "+f"(d[0]), "+f"(d[1]), "+f"(d[2]), "+f"(d[3])
        : "r"(a0), "r"(a1), "r"(a2), "r"(a3), "r"(b0), "r"(b1));
}

// ---------------------------------------------------------------------------
// Raw-mma TF32 NT GEMM: R9/R12 shape + register double-buffered fragments.
// CTA 128x128, 4 warps (2x2 of 64x64), K-chunk 32, 3-stage cp.async,
// single sync per chunk, direct-to-global epilogue, 2 CTAs/SM.
// ---------------------------------------------------------------------------
#define LDA 36
#define STAGE_F (128 * LDA)
#define GEMM_SMEM (3 * 2 * STAGE_F * 4)

template<int EPI>
__global__ void __launch_bounds__(128, 2) gemm_mma(
    const float* __restrict__ A, const float* __restrict__ B,
    const float* __restrict__ bias, const float* __restrict__ res,
    float* __restrict__ C, int M, int N, int K)
{
    extern __shared__ float smem[];

    const int tid  = threadIdx.x;
    const int w    = tid >> 5;
    const int lane = tid & 31;
    const int bm = blockIdx.y, bn = blockIdx.x;
    const int wm = w & 1;
    const int wn = w >> 1;

    const float* Abase = A + (size_t)(bm * 128) * K;
    const float* Bbase = B + (size_t)(bn * 128) * K;

    const uint32_t smem_u32 = (uint32_t)__cvta_generic_to_shared(smem);

    const int arow_l = lane & 15;
    const int acol_l = (lane >> 4) << 2;
    const int brow_l = (lane & 7) + ((lane >> 4) << 3);
    const int bcol_l = ((lane >> 3) & 1) << 2;

    float acc[4][8][4];
#pragma unroll
    for (int i = 0; i < 4; i++)
#pragma unroll
        for (int j = 0; j < 8; j++)
#pragma unroll
            for (int e = 0; e < 4; e++) acc[i][j][e] = 0.f;

    const int KC = K >> 5;

    auto issue = [&](int c, int s) {
        const int k0 = c << 5;
        const uint32_t sbase = smem_u32 + (uint32_t)(s * 2 * STAGE_F) * 4u;
#pragma unroll
        for (int i = 0; i < 8; i++) {
            int idx = tid + i * 128, r = idx >> 3, cc = idx & 7;
            cp_async16(sbase + (uint32_t)(r * LDA + cc * 4) * 4u,
                       Abase + (size_t)r * K + k0 + cc * 4);
        }
#pragma unroll
        for (int i = 0; i < 8; i++) {
            int idx = tid + i * 128, r = idx >> 3, cc = idx & 7;
            cp_async16(sbase + (uint32_t)(STAGE_F + r * LDA + cc * 4) * 4u,
                       Bbase + (size_t)r * K + k0 + cc * 4);
        }
    };

    issue(0, 0); cp_commit();
    issue(1, 1); cp_commit();

    int s3 = 2;
    for (int c = 0; c < KC; c++) {
        cp_wait1();
        __syncthreads();
        if (c + 2 < KC) issue(c + 2, s3);
        cp_commit();
        s3 = (s3 == 2) ? 0 : s3 + 1;

        const uint32_t soff = (uint32_t)((c % 3) * 2 * STAGE_F) * 4u;
        const uint32_t abase = smem_u32 + soff +
            (uint32_t)((wm * 64 + arow_l) * LDA + acol_l) * 4u;
        const uint32_t bbase = smem_u32 + soff + (uint32_t)STAGE_F * 4u +
            (uint32_t)((wn * 64 + brow_l) * LDA + bcol_l) * 4u;

        // register double-buffered fragment pipeline over 4 kk-steps
        uint32_t a[2][4][4], b[2][4][4];
#pragma unroll
        for (int i = 0; i < 4; i++)
            ldsm4(a[0][i][0], a[0][i][1], a[0][i][2], a[0][i][3],
                  abase + (uint32_t)(i * 16 * LDA) * 4u);
#pragma unroll
        for (int j = 0; j < 4; j++)
            ldsm4(b[0][j][0], b[0][j][1], b[0][j][2], b[0][j][3],
                  bbase + (uint32_t)(j * 16 * LDA) * 4u);

#pragma unroll
        for (int k8 = 0; k8 < 4; k8++) {
            const int cur = k8 & 1, nxt = cur ^ 1;
            if (k8 < 3) {
                const uint32_t kk = (uint32_t)((k8 + 1) * 8) * 4u;
#pragma unroll
                for (int i = 0; i < 4; i++)
                    ldsm4(a[nxt][i][0], a[nxt][i][1], a[nxt][i][2], a[nxt][i][3],
                          abase + (uint32_t)(i * 16 * LDA) * 4u + kk);
#pragma unroll
                for (int j = 0; j < 4; j++)
                    ldsm4(b[nxt][j][0], b[nxt][j][1], b[nxt][j][2], b[nxt][j][3],
                          bbase + (uint32_t)(j * 16 * LDA) * 4u + kk);
            }
#pragma unroll
            for (int i = 0; i < 4; i++)
#pragma unroll
                for (int j = 0; j < 4; j++) {
                    mma8(acc[i][2 * j],
                         a[cur][i][0], a[cur][i][1], a[cur][i][2], a[cur][i][3],
                         b[cur][j][0], b[cur][j][1]);
                    mma8(acc[i][2 * j + 1],
                         a[cur][i][0], a[cur][i][1], a[cur][i][2], a[cur][i][3],
                         b[cur][j][2], b[cur][j][3]);
                }
        }
    }

    // direct-to-global epilogue
    const int gr0 = bm * 128 + wm * 64 + (lane >> 2);
    const int gc0 = bn * 128 + wn * 64 + 2 * (lane & 3);

#pragma unroll
    for (int i = 0; i < 4; i++) {
        const int r0 = gr0 + i * 16;
        const int r1 = r0 + 8;
#pragma unroll
        for (int jj = 0; jj < 8; jj++) {
            const int col = gc0 + jj * 8;
            float* d = acc[i][jj];
            float v0 = d[0], v1 = d[1], v2 = d[2], v3 = d[3];
            if (EPI == 1) {
                float b0 = bias[col], b1 = bias[col + 1];
                const float* rr0 = res + (size_t)r0 * N + col;
                const float* rr1 = res + (size_t)r1 * N + col;
                v0 += b0 + rr0[0]; v1 += b1 + rr0[1];
                v2 += b0 + rr1[0]; v3 += b1 + rr1[1];
            } else if (EPI == 2) {
                float b0 = bias[col], b1 = bias[col + 1];
                v0 += b0; v1 += b1; v2 += b0; v3 += b1;
                v0 = wmma::__float_to_tf32(0.5f * v0 * (1.0f + erff(v0 * 0.70710678118654752f)));
                v1 = wmma::__float_to_tf32(0.5f * v1 * (1.0f + erff(v1 * 0.70710678118654752f)));
                v2 = wmma::__float_to_tf32(0.5f * v2 * (1.0f + erff(v2 * 0.70710678118654752f)));
                v3 = wmma::__float_to_tf32(0.5f * v3 * (1.0f + erff(v3 * 0.70710678118654752f)));
            }
            *(float2*)(C + (size_t)r0 * N + col) = make_float2(v0, v1);
            *(float2*)(C + (size_t)r1 * N + col) = make_float2(v2, v3);
        }
    }
}

// ---------------------------------------------------------------------------
// Split LayerNorm (unchanged)
// ---------------------------------------------------------------------------
__global__ void __launch_bounds__(128) ln_split_kernel(
    const float* __restrict__ x,
    const float* __restrict__ ga, const float* __restrict__ ba,
    const float* __restrict__ gb, const float* __restrict__ bb,
    const float* __restrict__ gc, const float* __restrict__ bc,
    float* __restrict__ out)
{
    __shared__ float xs[DIM];
    __shared__ float st_m[3];
    __shared__ float st_r[3];

    const int row = blockIdx.x;
    const int tid = threadIdx.x;
    const int w = tid >> 5, lane = tid & 31;

    const float4* xr4 = (const float4*)(x + (size_t)row * DIM);
    float4* xs4 = (float4*)xs;
    xs4[tid] = xr4[tid];
    if (tid < 64) xs4[128 + tid] = xr4[128 + tid];
    __syncthreads();

    if (w < 3) {
        const int lo  = (w == 0) ? 0 : ((w == 1) ? S1V : S2V);
        const int hi  = (w == 0) ? S1V : ((w == 1) ? S2V : DIM);
        float s1 = 0.f, s2 = 0.f;
        for (int i = lo + lane; i < hi; i += 32) {
            float v = xs[i];
            s1 += v; s2 += v * v;
        }
#pragma unroll
        for (int off = 16; off > 0; off >>= 1) {
            s1 += __shfl_xor_sync(0xffffffffu, s1, off);
            s2 += __shfl_xor_sync(0xffffffffu, s2, off);
        }
        if (lane == 0) {
            float len = (float)(hi - lo);
            float m = s1 / len;
            float var = s2 / len - m * m;
            st_m[w] = m;
            st_r[w] = rsqrtf(var + EPS);
        }
    }
    __syncthreads();

    float* orow = out + (size_t)row * DIM;
    for (int i = tid; i < DIM; i += 128) {
        int s = (i < S1V) ? 0 : ((i < S2V) ? 1 : 2);
        int li = i - ((s == 0) ? 0 : ((s == 1) ? S1V : S2V));
        const float* g  = (s == 0) ? ga : ((s == 1) ? gb : gc);
        const float* be = (s == 0) ? ba : ((s == 1) ? bb : bc);
        float v = (xs[i] - st_m[s]) * st_r[s] * g[li] + be[li];
        orow[i] = wmma::__float_to_tf32(v);
    }
}

// ---------------------------------------------------------------------------
// Tensor-core flash attention — exact R12 scalar version (proven 252us).
// Block = 128 threads (4 warps), 64 q-rows, 64-key tiles.
// smem: qs[64][68], ks[64][68] (reused for P), vs[64][72]
// ---------------------------------------------------------------------------
#define ALDK 68
#define ALDV 72
#define ATTN_SMEM ((2 * 64 * ALDK + 64 * ALDV) * 4)

__global__ void __launch_bounds__(128) attn_kernel(
    const float* __restrict__ qkv, float* __restrict__ y)
{
    extern __shared__ float sm[];
    float* qs = sm;
    float* ks = sm + 64 * ALDK;
    float* vs = sm + 2 * 64 * ALDK;

    const int tid  = threadIdx.x;
    const int w    = tid >> 5;
    const int lane = tid & 31;
    const int qr   = lane >> 2;
    const int qc   = lane & 3;
    const int n0 = blockIdx.x * 64;
    const int b = blockIdx.y / NHEAD;
    const int h = blockIdx.y % NHEAD;

    const float* base = qkv + (size_t)b * SEQ * (3 * DIM) + h * HD;

    for (int i = tid; i < 64 * 16; i += 128) {
        int r = i >> 4, c4 = (i & 15) * 4;
        *(float4*)(qs + r * ALDK + c4) =
            *(const float4*)(base + (size_t)(n0 + r) * (3 * DIM) + c4);
    }

    float o[8][4];
    float m0 = -INFINITY, m1 = -INFINITY, l0 = 0.f, l1 = 0.f;
#pragma unroll
    for (int j = 0; j < 8; j++)
#pragma unroll
        for (int e = 0; e < 4; e++) o[j][e] = 0.f;

    const int rowA = (w * 16 + qr) * ALDK;
    const int rowB = rowA + 8 * ALDK;

    for (int kt = 0; kt < SEQ / 64; kt++) {
        for (int i = tid; i < 64 * 16; i += 128) {
            int r = i >> 4, c4 = (i & 15) * 4;
            const float* kp = base + DIM + (size_t)(kt * 64 + r) * (3 * DIM) + c4;
            *(float4*)(ks + r * ALDK + c4) = *(const float4*)kp;
            *(float4*)(vs + r * ALDV + c4) = *(const float4*)(kp + DIM);
        }
        __syncthreads();

        float s[8][4];
#pragma unroll
        for (int j = 0; j < 8; j++)
#pragma unroll
            for (int e = 0; e < 4; e++) s[j][e] = 0.f;

#pragma unroll
        for (int k8 = 0; k8 < 8; k8++) {
            const int kb = k8 * 8;
            uint32_t a0 = __float_as_uint(qs[rowA + kb + qc]);
            uint32_t a1 = __float_as_uint(qs[rowB + kb + qc]);
            uint32_t a2 = __float_as_uint(qs[rowA + kb + qc + 4]);
            uint32_t a3 = __float_as_uint(qs[rowB + kb + qc + 4]);
#pragma unroll
            for (int j = 0; j < 8; j++) {
                uint32_t b0 = __float_as_uint(ks[(j * 8 + qr) * ALDK + kb + qc]);
                uint32_t b1 = __float_as_uint(ks[(j * 8 + qr) * ALDK + kb + qc + 4]);
                mma8(s[j], a0, a1, a2, a3, b0, b1);
            }
        }
        __syncthreads();

        float mx0 = -INFINITY, mx1 = -INFINITY;
#pragma unroll
        for (int j = 0; j < 8; j++) {
#pragma unroll
            for (int e = 0; e < 4; e++) s[j][e] *= SCALE;
            mx0 = fmaxf(mx0, fmaxf(s[j][0], s[j][1]));
            mx1 = fmaxf(mx1, fmaxf(s[j][2], s[j][3]));
        }
        mx0 = fmaxf(mx0, __shfl_xor_sync(0xffffffffu, mx0, 1));
        mx0 = fmaxf(mx0, __shfl_xor_sync(0xffffffffu, mx0, 2));
        mx1 = fmaxf(mx1, __shfl_xor_sync(0xffffffffu, mx1, 1));
        mx1 = fmaxf(mx1, __shfl_xor_sync(0xffffffffu, mx1, 2));

        float mn0 = fmaxf(m0, mx0), mn1 = fmaxf(m1, mx1);
        float c0 = __expf(m0 - mn0), c1 = __expf(m1 - mn1);
        float rs0 = 0.f, rs1 = 0.f;

#pragma unroll
        for (int j = 0; j < 8; j++) {
            float p0 = __expf(s[j][0] - mn0);
            float p1 = __expf(s[j][1] - mn0);
            float p2 = __expf(s[j][2] - mn1);
            float p3 = __expf(s[j][3] - mn1);
            rs0 += p0 + p1; rs1 += p2 + p3;
            float* pr0 = ks + rowA + j * 8 + qc * 2;
            float* pr1 = ks + rowB + j * 8 + qc * 2;
            pr0[0] = p0; pr0[1] = p1;
            pr1[0] = p2; pr1[1] = p3;
            o[j][0] *= c0; o[j][1] *= c0; o[j][2] *= c1; o[j][3] *= c1;
        }
        rs0 += __shfl_xor_sync(0xffffffffu, rs0, 1);
        rs0 += __shfl_xor_sync(0xffffffffu, rs0, 2);
        rs1 += __shfl_xor_sync(0xffffffffu, rs1, 1);
        rs1 += __shfl_xor_sync(0xffffffffu, rs1, 2);
        l0 = l0 * c0 + rs0; l1 = l1 * c1 + rs1;
        m0 = mn0; m1 = mn1;
        __syncwarp();

#pragma unroll
        for (int k8 = 0; k8 < 8; k8++) {
            const int kb = k8 * 8;
            uint32_t a0 = __float_as_uint(ks[rowA + kb + qc]);
            uint32_t a1 = __float_as_uint(ks[rowB + kb + qc]);
            uint32_t a2 = __float_as_uint(ks[rowA + kb + qc + 4]);
            uint32_t a3 = __float_as_uint(ks[rowB + kb + qc + 4]);
#pragma unroll
            for (int j = 0; j < 8; j++) {
                uint32_t b0 = __float_as_uint(vs[(kb + qc) * ALDV + j * 8 + qr]);
                uint32_t b1 = __float_as_uint(vs[(kb + qc + 4) * ALDV + j * 8 + qr]);
                mma8(o[j], a0, a1, a2, a3, b0, b1);
            }
        }
        __syncthreads();
    }

    const float i0 = 1.0f / l0, i1 = 1.0f / l1;
    const int gr0 = b * SEQ + n0 + w * 16 + qr;
    float* y0 = y + (size_t)gr0 * DIM + h * HD;
    float* y1 = y0 + (size_t)8 * DIM;
#pragma unroll
    for (int j = 0; j < 8; j++) {
        const int cb = j * 8 + qc * 2;
        y0[cb]     = wmma::__float_to_tf32(o[j][0] * i0);
        y0[cb + 1] = wmma::__float_to_tf32(o[j][1] * i0);
        y1[cb]     = wmma::__float_to_tf32(o[j][2] * i1);
        y1[cb + 1] = wmma::__float_to_tf32(o[j][3] * i1);
    }
}

// ---------------------------------------------------------------------------
// Launch
// ---------------------------------------------------------------------------
extern "C" void kernel_launch(void* const* d_in, const int* in_sizes, int n_in,
                              void* d_out, int out_size)
{
    const float* x      = (const float*)d_in[0];
    const float* ln1a_g = (const float*)d_in[1];
    const float* ln1a_b = (const float*)d_in[2];
    const float* ln1b_g = (const float*)d_in[3];
    const float* ln1b_b = (const float*)d_in[4];
    const float* ln1c_g = (const float*)d_in[5];
    const float* ln1c_b = (const float*)d_in[6];
    const float* ln2a_g = (const float*)d_in[7];
    const float* ln2a_b = (const float*)d_in[8];
    const float* ln2b_g = (const float*)d_in[9];
    const float* ln2b_b = (const float*)d_in[10];
    const float* ln2c_g = (const float*)d_in[11];
    const float* ln2c_b = (const float*)d_in[12];
    const float* qkv_w  = (const float*)d_in[13];
    const float* proj_w = (const float*)d_in[14];
    const float* proj_b = (const float*)d_in[15];
    const float* fc1_w  = (const float*)d_in[16];
    const float* fc1_b  = (const float*)d_in[17];
    const float* fc2_w  = (const float*)d_in[18];
    const float* fc2_b  = (const float*)d_in[19];
    float* out = (float*)d_out;

    float *p_normx, *p_qkv, *p_y, *p_h, *p_wq, *p_wp, *p_w1, *p_w2;
    cudaGetSymbolAddress((void**)&p_normx, g_normx);
    cudaGetSymbolAddress((void**)&p_qkv,   g_qkv);
    cudaGetSymbolAddress((void**)&p_y,     g_y);
    cudaGetSymbolAddress((void**)&p_h,     g_h);
    cudaGetSymbolAddress((void**)&p_wq,    g_wq);
    cudaGetSymbolAddress((void**)&p_wp,    g_wp);
    cudaGetSymbolAddress((void**)&p_w1,    g_w1);
    cudaGetSymbolAddress((void**)&p_w2,    g_w2);

    cudaFuncSetAttribute(attn_kernel,
                         cudaFuncAttributeMaxDynamicSharedMemorySize, ATTN_SMEM);
    cudaFuncSetAttribute(gemm_mma<0>,
                         cudaFuncAttributeMaxDynamicSharedMemorySize, GEMM_SMEM);
    cudaFuncSetAttribute(gemm_mma<1>,
                         cudaFuncAttributeMaxDynamicSharedMemorySize, GEMM_SMEM);
    cudaFuncSetAttribute(gemm_mma<2>,
                         cudaFuncAttributeMaxDynamicSharedMemorySize, GEMM_SMEM);

    // 0. round all weights to tf32 (RN) in one launch
    round_all_kernel<<<(NTOT4 + 255) / 256, 256>>>(
        qkv_w, p_wq, proj_w, p_wp, fc1_w, p_w1, fc2_w, p_w2);

    // 1. norm1
    ln_split_kernel<<<TOK, 128>>>(x, ln1a_g, ln1a_b, ln1b_g, ln1b_b,
                                  ln1c_g, ln1c_b, p_normx);

    // 2. QKV
    gemm_mma<0><<<dim3(3 * DIM / 128, TOK / 128), 128, GEMM_SMEM>>>(
        p_normx, p_wq, nullptr, nullptr, p_qkv, TOK, 3 * DIM, DIM);

    // 3. attention
    attn_kernel<<<dim3(SEQ / 64, BATCH * NHEAD), 128, ATTN_SMEM>>>(p_qkv, p_y);

    // 4. proj + bias + residual(x)
    gemm_mma<1><<<dim3(DIM / 128, TOK / 128), 128, GEMM_SMEM>>>(
        p_y, p_wp, proj_b, x, out, TOK, DIM, DIM);

    // 5. norm2
    ln_split_kernel<<<TOK, 128>>>(out, ln2a_g, ln2a_b, ln2b_g, ln2b_b,
                                  ln2c_g, ln2c_b, p_normx);

    // 6. FC1 + bias + GELU
    gemm_mma<2><<<dim3(HID / 128, TOK / 128), 128, GEMM_SMEM>>>(
        p_normx, p_w1, fc1_b, nullptr, p_h, TOK, HID, DIM);

    // 7. FC2 + bias + residual(out)
    gemm_mma<1><<<dim3(DIM / 128, TOK / 128), 128, GEMM_SMEM>>>(
        p_h, p_w2, fc2_b, out, out, TOK, DIM, HID);
}

// round 16
// speedup vs baseline: 1.0510x; 1.0272x over previous
#include <cuda_runtime.h>
#include <math.h>
#include <stdint.h>
#include <mma.h>

using namespace nvcuda;

// ---------------------------------------------------------------------------
// Problem constants
// ---------------------------------------------------------------------------
#define DIM   768
#define NHEAD 12
#define HD    64
#define BATCH 8
#define SEQ   1024
#define TOK   (BATCH*SEQ)
#define HID   3072
#define S1V   320
#define S2V   384
#define EPS   1e-5f
#define SCALE 0.125f

// ---------------------------------------------------------------------------
// Scratch
// ---------------------------------------------------------------------------
__device__ float g_normx[TOK * DIM];
__device__ float g_qkv  [TOK * 3 * DIM];
__device__ float g_y    [TOK * DIM];
__device__ float g_h    [TOK * HID];
__device__ float g_wq[3 * DIM * DIM];
__device__ float g_wp[DIM * DIM];
__device__ float g_w1[HID * DIM];
__device__ float g_w2[DIM * HID];

// ---------------------------------------------------------------------------
// Fused weight rounding
// ---------------------------------------------------------------------------
#define NQ4 (3 * DIM * DIM / 4)
#define NP4 (DIM * DIM / 4)
#define N14 (HID * DIM / 4)
#define N24 (DIM * HID / 4)
#define NTOT4 (NQ4 + NP4 + N14 + N24)

__global__ void __launch_bounds__(256) round_all_kernel(
    const float* __restrict__ sq, float* __restrict__ dq,
    const float* __restrict__ sp, float* __restrict__ dp,
    const float* __restrict__ s1, float* __restrict__ d1,
    const float* __restrict__ s2, float* __restrict__ d2)
{
    int i = blockIdx.x * 256 + threadIdx.x;
    if (i >= NTOT4) return;
    const float4* src;
    float4* dst;
    int off;
    if (i < NQ4)                  { src = (const float4*)sq; dst = (float4*)dq; off = i; }
    else if (i < NQ4 + NP4)       { src = (const float4*)sp; dst = (float4*)dp; off = i - NQ4; }
    else if (i < NQ4 + NP4 + N14) { src = (const float4*)s1; dst = (float4*)d1; off = i - NQ4 - NP4; }
    else                          { src = (const float4*)s2; dst = (float4*)d2; off = i - NQ4 - NP4 - N14; }
    float4 v = src[off];
    v.x = wmma::__float_to_tf32(v.x);
    v.y = wmma::__float_to_tf32(v.y);
    v.z = wmma::__float_to_tf32(v.z);
    v.w = wmma::__float_to_tf32(v.w);
    dst[off] = v;
}

// ---------------------------------------------------------------------------
// PTX helpers
// ---------------------------------------------------------------------------
__device__ __forceinline__ void cp_async16(uint32_t dst, const float* src) {
    asm volatile("cp.async.cg.shared.global [%0], [%1], 16;\n"
                 :: "r"(dst), "l"(src));
}
__device__ __forceinline__ void cp_commit() {
    asm volatile("cp.async.commit_group;\n" ::: "memory");
}
__device__ __forceinline__ void cp_wait1() {
    asm volatile("cp.async.wait_group 1;\n" ::: "memory");
}
__device__ __forceinline__ void ldsm4(uint32_t& r0, uint32_t& r1,
                                      uint32_t& r2, uint32_t& r3, uint32_t addr) {
    asm volatile("ldmatrix.sync.aligned.m8n8.x4.shared.b16 {%0,%1,%2,%3}, [%4];"
                 : "=r"(r0), "=r"(r1), "=r"(r2), "=r"(r3) : "r"(addr));
}
__device__ __forceinline__ void mma8(float* d,
    uint32_t a0, uint32_t a1, uint32_t a2, uint32_t a3,
    uint32_t b0, uint32_t b1)
{
    asm volatile(
        "mma.sync.aligned.m16n8k8.row.col.f32.tf32.tf32.f32 "
        "{%0,%1,%2,%3},{%4,%5,%6,%7},{%8,%9},{%0,%1,%2,%3};"
        : "+f"(d[0]), "+f"(d[1]), "+f"(d[2]), "+f"(d[3])
        : "r"(a0), "r"(a1), "r"(a2), "r"(a3), "r"(b0), "r"(b1));
}

__device__ __forceinline__ float gelu_tf32(float x) {
    return wmma::__float_to_tf32(0.5f * x * (1.0f + erff(x * 0.70710678118654752f)));
}

// ---------------------------------------------------------------------------
// Raw-mma TF32 NT GEMM, CTA 128x128 (proven R12 config) — QKV / FC1.
// ---------------------------------------------------------------------------
#define LDA 36
#define STAGE_F (128 * LDA)
#define GEMM_SMEM (3 * 2 * STAGE_F * 4)

template<int EPI>
__global__ void __launch_bounds__(128, 2) gemm_mma(
    const float* __restrict__ A, const float* __restrict__ B,
    const float* __restrict__ bias, const float* __restrict__ res,
    float* __restrict__ C, int M, int N, int K)
{
    extern __shared__ float smem[];

    const int tid  = threadIdx.x;
    const int w    = tid >> 5;
    const int lane = tid & 31;
    const int bm = blockIdx.y, bn = blockIdx.x;
    const int wm = w & 1;
    const int wn = w >> 1;

    const float* Abase = A + (size_t)(bm * 128) * K;
    const float* Bbase = B + (size_t)(bn * 128) * K;

    const uint32_t smem_u32 = (uint32_t)__cvta_generic_to_shared(smem);

    const int arow_l = lane & 15;
    const int acol_l = (lane >> 4) << 2;
    const int brow_l = (lane & 7) + ((lane >> 4) << 3);
    const int bcol_l = ((lane >> 3) & 1) << 2;

    float acc[4][8][4];
#pragma unroll
    for (int i = 0; i < 4; i++)
#pragma unroll
        for (int j = 0; j < 8; j++)
#pragma unroll
            for (int e = 0; e < 4; e++) acc[i][j][e] = 0.f;

    const int KC = K >> 5;

    auto issue = [&](int c, int s) {
        const int k0 = c << 5;
        const uint32_t sbase = smem_u32 + (uint32_t)(s * 2 * STAGE_F) * 4u;
#pragma unroll
        for (int i = 0; i < 8; i++) {
            int idx = tid + i * 128, r = idx >> 3, cc = idx & 7;
            cp_async16(sbase + (uint32_t)(r * LDA + cc * 4) * 4u,
                       Abase + (size_t)r * K + k0 + cc * 4);
        }
#pragma unroll
        for (int i = 0; i < 8; i++) {
            int idx = tid + i * 128, r = idx >> 3, cc = idx & 7;
            cp_async16(sbase + (uint32_t)(STAGE_F + r * LDA + cc * 4) * 4u,
                       Bbase + (size_t)r * K + k0 + cc * 4);
        }
    };

    issue(0, 0); cp_commit();
    issue(1, 1); cp_commit();

    int s3 = 2;
    for (int c = 0; c < KC; c++) {
        cp_wait1();
        __syncthreads();
        if (c + 2 < KC) issue(c + 2, s3);
        cp_commit();
        s3 = (s3 == 2) ? 0 : s3 + 1;

        const uint32_t soff = (uint32_t)((c % 3) * 2 * STAGE_F) * 4u;
        const uint32_t abase = smem_u32 + soff +
            (uint32_t)((wm * 64 + arow_l) * LDA + acol_l) * 4u;
        const uint32_t bbase = smem_u32 + soff + (uint32_t)STAGE_F * 4u +
            (uint32_t)((wn * 64 + brow_l) * LDA + bcol_l) * 4u;

#pragma unroll
        for (int kk = 0; kk < 32; kk += 8) {
            uint32_t a[4][4], b[4][4];
#pragma unroll
            for (int i = 0; i < 4; i++)
                ldsm4(a[i][0], a[i][1], a[i][2], a[i][3],
                      abase + (uint32_t)(i * 16 * LDA + kk) * 4u);
#pragma unroll
            for (int j = 0; j < 4; j++)
                ldsm4(b[j][0], b[j][1], b[j][2], b[j][3],
                      bbase + (uint32_t)(j * 16 * LDA + kk) * 4u);
#pragma unroll
            for (int i = 0; i < 4; i++)
#pragma unroll
                for (int j = 0; j < 4; j++) {
                    mma8(acc[i][2 * j],     a[i][0], a[i][1], a[i][2], a[i][3],
                         b[j][0], b[j][1]);
                    mma8(acc[i][2 * j + 1], a[i][0], a[i][1], a[i][2], a[i][3],
                         b[j][2], b[j][3]);
                }
        }
    }

    const int gr0 = bm * 128 + wm * 64 + (lane >> 2);
    const int gc0 = bn * 128 + wn * 64 + 2 * (lane & 3);

#pragma unroll
    for (int i = 0; i < 4; i++) {
        const int r0 = gr0 + i * 16;
        const int r1 = r0 + 8;
#pragma unroll
        for (int jj = 0; jj < 8; jj++) {
            const int col = gc0 + jj * 8;
            float* d = acc[i][jj];
            float v0 = d[0], v1 = d[1], v2 = d[2], v3 = d[3];
            if (EPI == 1) {
                float b0 = bias[col], b1 = bias[col + 1];
                const float* rr0 = res + (size_t)r0 * N + col;
                const float* rr1 = res + (size_t)r1 * N + col;
                v0 += b0 + rr0[0]; v1 += b1 + rr0[1];
                v2 += b0 + rr1[0]; v3 += b1 + rr1[1];
            } else if (EPI == 2) {
                float b0 = bias[col], b1 = bias[col + 1];
                v0 = gelu_tf32(v0 + b0); v1 = gelu_tf32(v1 + b1);
                v2 = gelu_tf32(v2 + b0); v3 = gelu_tf32(v3 + b1);
            }
            *(float2*)(C + (size_t)r0 * N + col) = make_float2(v0, v1);
            *(float2*)(C + (size_t)r1 * N + col) = make_float2(v2, v3);
        }
    }
}

// ---------------------------------------------------------------------------
// Raw-mma TF32 NT GEMM, CTA 64x128 — proj / FC2 (wave-quantization fix).
// 4 warps (2x2 of 32x64), K-chunk 32, 3-stage cp.async, single sync/chunk.
// ---------------------------------------------------------------------------
#define STAGE_A64 (64 * LDA)
#define STAGE_T64 (STAGE_A64 + 128 * LDA)
#define GEMM_SMEM64 (3 * STAGE_T64 * 4)

template<int EPI>
__global__ void __launch_bounds__(128, 2) gemm_mma64(
    const float* __restrict__ A, const float* __restrict__ B,
    const float* __restrict__ bias, const float* __restrict__ res,
    float* __restrict__ C, int M, int N, int K)
{
    extern __shared__ float smem[];

    const int tid  = threadIdx.x;
    const int w    = tid >> 5;
    const int lane = tid & 31;
    const int bm = blockIdx.y, bn = blockIdx.x;
    const int wm = w & 1;       // 2 m-slices of 32
    const int wn = w >> 1;      // 2 n-slices of 64

    const float* Abase = A + (size_t)(bm * 64) * K;
    const float* Bbase = B + (size_t)(bn * 128) * K;

    const uint32_t smem_u32 = (uint32_t)__cvta_generic_to_shared(smem);

    const int arow_l = lane & 15;
    const int acol_l = (lane >> 4) << 2;
    const int brow_l = (lane & 7) + ((lane >> 4) << 3);
    const int bcol_l = ((lane >> 3) & 1) << 2;

    float acc[2][8][4];
#pragma unroll
    for (int i = 0; i < 2; i++)
#pragma unroll
        for (int j = 0; j < 8; j++)
#pragma unroll
            for (int e = 0; e < 4; e++) acc[i][j][e] = 0.f;

    const int KC = K >> 5;

    auto issue = [&](int c, int s) {
        const int k0 = c << 5;
        const uint32_t sbase = smem_u32 + (uint32_t)(s * STAGE_T64) * 4u;
#pragma unroll
        for (int i = 0; i < 4; i++) {           // A: 64 rows x 8 f4 = 512
            int idx = tid + i * 128, r = idx >> 3, cc = idx & 7;
            cp_async16(sbase + (uint32_t)(r * LDA + cc * 4) * 4u,
                       Abase + (size_t)r * K + k0 + cc * 4);
        }
#pragma unroll
        for (int i = 0; i < 8; i++) {           // B: 128 rows x 8 f4 = 1024
            int idx = tid + i * 128, r = idx >> 3, cc = idx & 7;
            cp_async16(sbase + (uint32_t)(STAGE_A64 + r * LDA + cc * 4) * 4u,
                       Bbase + (size_t)r * K + k0 + cc * 4);
        }
    };

    issue(0, 0); cp_commit();
    issue(1, 1); cp_commit();

    int s3 = 2;
    for (int c = 0; c < KC; c++) {
        cp_wait1();
        __syncthreads();
        if (c + 2 < KC) issue(c + 2, s3);
        cp_commit();
        s3 = (s3 == 2) ? 0 : s3 + 1;

        const uint32_t soff = (uint32_t)((c % 3) * STAGE_T64) * 4u;
        const uint32_t abase = smem_u32 + soff +
            (uint32_t)((wm * 32 + arow_l) * LDA + acol_l) * 4u;
        const uint32_t bbase = smem_u32 + soff + (uint32_t)STAGE_A64 * 4u +
            (uint32_t)((wn * 64 + brow_l) * LDA + bcol_l) * 4u;

#pragma unroll
        for (int kk = 0; kk < 32; kk += 8) {
            uint32_t a[2][4], b[4][4];
#pragma unroll
            for (int i = 0; i < 2; i++)
                ldsm4(a[i][0], a[i][1], a[i][2], a[i][3],
                      abase + (uint32_t)(i * 16 * LDA + kk) * 4u);
#pragma unroll
            for (int j = 0; j < 4; j++)
                ldsm4(b[j][0], b[j][1], b[j][2], b[j][3],
                      bbase + (uint32_t)(j * 16 * LDA + kk) * 4u);
#pragma unroll
            for (int i = 0; i < 2; i++)
#pragma unroll
                for (int j = 0; j < 4; j++) {
                    mma8(acc[i][2 * j],     a[i][0], a[i][1], a[i][2], a[i][3],
                         b[j][0], b[j][1]);
                    mma8(acc[i][2 * j + 1], a[i][0], a[i][1], a[i][2], a[i][3],
                         b[j][2], b[j][3]);
                }
        }
    }

    const int gr0 = bm * 64 + wm * 32 + (lane >> 2);
    const int gc0 = bn * 128 + wn * 64 + 2 * (lane & 3);

#pragma unroll
    for (int i = 0; i < 2; i++) {
        const int r0 = gr0 + i * 16;
        const int r1 = r0 + 8;
#pragma unroll
        for (int jj = 0; jj < 8; jj++) {
            const int col = gc0 + jj * 8;
            float* d = acc[i][jj];
            float v0 = d[0], v1 = d[1], v2 = d[2], v3 = d[3];
            if (EPI == 1) {
                float b0 = bias[col], b1 = bias[col + 1];
                const float* rr0 = res + (size_t)r0 * N + col;
                const float* rr1 = res + (size_t)r1 * N + col;
                v0 += b0 + rr0[0]; v1 += b1 + rr0[1];
                v2 += b0 + rr1[0]; v3 += b1 + rr1[1];
            } else if (EPI == 2) {
                float b0 = bias[col], b1 = bias[col + 1];
                v0 = gelu_tf32(v0 + b0); v1 = gelu_tf32(v1 + b1);
                v2 = gelu_tf32(v2 + b0); v3 = gelu_tf32(v3 + b1);
            }
            *(float2*)(C + (size_t)r0 * N + col) = make_float2(v0, v1);
            *(float2*)(C + (size_t)r1 * N + col) = make_float2(v2, v3);
        }
    }
}

// ---------------------------------------------------------------------------
// Split LayerNorm (unchanged)
// ---------------------------------------------------------------------------
__global__ void __launch_bounds__(128) ln_split_kernel(
    const float* __restrict__ x,
    const float* __restrict__ ga, const float* __restrict__ ba,
    const float* __restrict__ gb, const float* __restrict__ bb,
    const float* __restrict__ gc, const float* __restrict__ bc,
    float* __restrict__ out)
{
    __shared__ float xs[DIM];
    __shared__ float st_m[3];
    __shared__ float st_r[3];

    const int row = blockIdx.x;
    const int tid = threadIdx.x;
    const int w = tid >> 5, lane = tid & 31;

    const float4* xr4 = (const float4*)(x + (size_t)row * DIM);
    float4* xs4 = (float4*)xs;
    xs4[tid] = xr4[tid];
    if (tid < 64) xs4[128 + tid] = xr4[128 + tid];
    __syncthreads();

    if (w < 3) {
        const int lo  = (w == 0) ? 0 : ((w == 1) ? S1V : S2V);
        const int hi  = (w == 0) ? S1V : ((w == 1) ? S2V : DIM);
        float s1 = 0.f, s2 = 0.f;
        for (int i = lo + lane; i < hi; i += 32) {
            float v = xs[i];
            s1 += v; s2 += v * v;
        }
#pragma unroll
        for (int off = 16; off > 0; off >>= 1) {
            s1 += __shfl_xor_sync(0xffffffffu, s1, off);
            s2 += __shfl_xor_sync(0xffffffffu, s2, off);
        }
        if (lane == 0) {
            float len = (float)(hi - lo);
            float m = s1 / len;
            float var = s2 / len - m * m;
            st_m[w] = m;
            st_r[w] = rsqrtf(var + EPS);
        }
    }
    __syncthreads();

    float* orow = out + (size_t)row * DIM;
    for (int i = tid; i < DIM; i += 128) {
        int s = (i < S1V) ? 0 : ((i < S2V) ? 1 : 2);
        int li = i - ((s == 0) ? 0 : ((s == 1) ? S1V : S2V));
        const float* g  = (s == 0) ? ga : ((s == 1) ? gb : gc);
        const float* be = (s == 0) ? ba : ((s == 1) ? bb : bc);
        float v = (xs[i] - st_m[s]) * st_r[s] * g[li] + be[li];
        orow[i] = wmma::__float_to_tf32(v);
    }
}

// ---------------------------------------------------------------------------
// Tensor-core flash attention — R12 scalar version (proven 252us, unchanged).
// ---------------------------------------------------------------------------
#define ALDK 68
#define ALDV 72
#define ATTN_SMEM ((2 * 64 * ALDK + 64 * ALDV) * 4)

__global__ void __launch_bounds__(128) attn_kernel(
    const float* __restrict__ qkv, float* __restrict__ y)
{
    extern __shared__ float sm[];
    float* qs = sm;
    float* ks = sm + 64 * ALDK;
    float* vs = sm + 2 * 64 * ALDK;

    const int tid  = threadIdx.x;
    const int w    = tid >> 5;
    const int lane = tid & 31;
    const int qr   = lane >> 2;
    const int qc   = lane & 3;
    const int n0 = blockIdx.x * 64;
    const int b = blockIdx.y / NHEAD;
    const int h = blockIdx.y % NHEAD;

    const float* base = qkv + (size_t)b * SEQ * (3 * DIM) + h * HD;

    for (int i = tid; i < 64 * 16; i += 128) {
        int r = i >> 4, c4 = (i & 15) * 4;
        *(float4*)(qs + r * ALDK + c4) =
            *(const float4*)(base + (size_t)(n0 + r) * (3 * DIM) + c4);
    }

    float o[8][4];
    float m0 = -INFINITY, m1 = -INFINITY, l0 = 0.f, l1 = 0.f;
#pragma unroll
    for (int j = 0; j < 8; j++)
#pragma unroll
        for (int e = 0; e < 4; e++) o[j][e] = 0.f;

    const int rowA = (w * 16 + qr) * ALDK;
    const int rowB = rowA + 8 * ALDK;

    for (int kt = 0; kt < SEQ / 64; kt++) {
        for (int i = tid; i < 64 * 16; i += 128) {
            int r = i >> 4, c4 = (i & 15) * 4;
            const float* kp = base + DIM + (size_t)(kt * 64 + r) * (3 * DIM) + c4;
            *(float4*)(ks + r * ALDK + c4) = *(const float4*)kp;
            *(float4*)(vs + r * ALDV + c4) = *(const float4*)(kp + DIM);
        }
        __syncthreads();

        float s[8][4];
#pragma unroll
        for (int j = 0; j < 8; j++)
#pragma unroll
            for (int e = 0; e < 4; e++) s[j][e] = 0.f;

#pragma unroll
        for (int k8 = 0; k8 < 8; k8++) {
            const int kb = k8 * 8;
            uint32_t a0 = __float_as_uint(qs[rowA + kb + qc]);
            uint32_t a1 = __float_as_uint(qs[rowB + kb + qc]);
            uint32_t a2 = __float_as_uint(qs[rowA + kb + qc + 4]);
            uint32_t a3 = __float_as_uint(qs[rowB + kb + qc + 4]);
#pragma unroll
            for (int j = 0; j < 8; j++) {
                uint32_t b0 = __float_as_uint(ks[(j * 8 + qr) * ALDK + kb + qc]);
                uint32_t b1 = __float_as_uint(ks[(j * 8 + qr) * ALDK + kb + qc + 4]);
                mma8(s[j], a0, a1, a2, a3, b0, b1);
            }
        }
        __syncthreads();

        float mx0 = -INFINITY, mx1 = -INFINITY;
#pragma unroll
        for (int j = 0; j < 8; j++) {
#pragma unroll
            for (int e = 0; e < 4; e++) s[j][e] *= SCALE;
            mx0 = fmaxf(mx0, fmaxf(s[j][0], s[j][1]));
            mx1 = fmaxf(mx1, fmaxf(s[j][2], s[j][3]));
        }
        mx0 = fmaxf(mx0, __shfl_xor_sync(0xffffffffu, mx0, 1));
        mx0 = fmaxf(mx0, __shfl_xor_sync(0xffffffffu, mx0, 2));
        mx1 = fmaxf(mx1, __shfl_xor_sync(0xffffffffu, mx1, 1));
        mx1 = fmaxf(mx1, __shfl_xor_sync(0xffffffffu, mx1, 2));

        float mn0 = fmaxf(m0, mx0), mn1 = fmaxf(m1, mx1);
        float c0 = __expf(m0 - mn0), c1 = __expf(m1 - mn1);
        float rs0 = 0.f, rs1 = 0.f;

#pragma unroll
        for (int j = 0; j < 8; j++) {
            float p0 = __expf(s[j][0] - mn0);
            float p1 = __expf(s[j][1] - mn0);
            float p2 = __expf(s[j][2] - mn1);
            float p3 = __expf(s[j][3] - mn1);
            rs0 += p0 + p1; rs1 += p2 + p3;
            float* pr0 = ks + rowA + j * 8 + qc * 2;
            float* pr1 = ks + rowB + j * 8 + qc * 2;
            pr0[0] = p0; pr0[1] = p1;
            pr1[0] = p2; pr1[1] = p3;
            o[j][0] *= c0; o[j][1] *= c0; o[j][2] *= c1; o[j][3] *= c1;
        }
        rs0 += __shfl_xor_sync(0xffffffffu, rs0, 1);
        rs0 += __shfl_xor_sync(0xffffffffu, rs0, 2);
        rs1 += __shfl_xor_sync(0xffffffffu, rs1, 1);
        rs1 += __shfl_xor_sync(0xffffffffu, rs1, 2);
        l0 = l0 * c0 + rs0; l1 = l1 * c1 + rs1;
        m0 = mn0; m1 = mn1;
        __syncwarp();

#pragma unroll
        for (int k8 = 0; k8 < 8; k8++) {
            const int kb = k8 * 8;
            uint32_t a0 = __float_as_uint(ks[rowA + kb + qc]);
            uint32_t a1 = __float_as_uint(ks[rowB + kb + qc]);
            uint32_t a2 = __float_as_uint(ks[rowA + kb + qc + 4]);
            uint32_t a3 = __float_as_uint(ks[rowB + kb + qc + 4]);
#pragma unroll
            for (int j = 0; j < 8; j++) {
                uint32_t b0 = __float_as_uint(vs[(kb + qc) * ALDV + j * 8 + qr]);
                uint32_t b1 = __float_as_uint(vs[(kb + qc + 4) * ALDV + j * 8 + qr]);
                mma8(o[j], a0, a1, a2, a3, b0, b1);
            }
        }
        __syncthreads();
    }

    const float i0 = 1.0f / l0, i1 = 1.0f / l1;
    const int gr0 = b * SEQ + n0 + w * 16 + qr;
    float* y0 = y + (size_t)gr0 * DIM + h * HD;
    float* y1 = y0 + (size_t)8 * DIM;
#pragma unroll
    for (int j = 0; j < 8; j++) {
        const int cb = j * 8 + qc * 2;
        y0[cb]     = wmma::__float_to_tf32(o[j][0] * i0);
        y0[cb + 1] = wmma::__float_to_tf32(o[j][1] * i0);
        y1[cb]     = wmma::__float_to_tf32(o[j][2] * i1);
        y1[cb + 1] = wmma::__float_to_tf32(o[j][3] * i1);
    }
}

// ---------------------------------------------------------------------------
// Launch
// ---------------------------------------------------------------------------
extern "C" void kernel_launch(void* const* d_in, const int* in_sizes, int n_in,
                              void* d_out, int out_size)
{
    const float* x      = (const float*)d_in[0];
    const float* ln1a_g = (const float*)d_in[1];
    const float* ln1a_b = (const float*)d_in[2];
    const float* ln1b_g = (const float*)d_in[3];
    const float* ln1b_b = (const float*)d_in[4];
    const float* ln1c_g = (const float*)d_in[5];
    const float* ln1c_b = (const float*)d_in[6];
    const float* ln2a_g = (const float*)d_in[7];
    const float* ln2a_b = (const float*)d_in[8];
    const float* ln2b_g = (const float*)d_in[9];
    const float* ln2b_b = (const float*)d_in[10];
    const float* ln2c_g = (const float*)d_in[11];
    const float* ln2c_b = (const float*)d_in[12];
    const float* qkv_w  = (const float*)d_in[13];
    const float* proj_w = (const float*)d_in[14];
    const float* proj_b = (const float*)d_in[15];
    const float* fc1_w  = (const float*)d_in[16];
    const float* fc1_b  = (const float*)d_in[17];
    const float* fc2_w  = (const float*)d_in[18];
    const float* fc2_b  = (const float*)d_in[19];
    float* out = (float*)d_out;

    float *p_normx, *p_qkv, *p_y, *p_h, *p_wq, *p_wp, *p_w1, *p_w2;
    cudaGetSymbolAddress((void**)&p_normx, g_normx);
    cudaGetSymbolAddress((void**)&p_qkv,   g_qkv);
    cudaGetSymbolAddress((void**)&p_y,     g_y);
    cudaGetSymbolAddress((void**)&p_h,     g_h);
    cudaGetSymbolAddress((void**)&p_wq,    g_wq);
    cudaGetSymbolAddress((void**)&p_wp,    g_wp);
    cudaGetSymbolAddress((void**)&p_w1,    g_w1);
    cudaGetSymbolAddress((void**)&p_w2,    g_w2);

    cudaFuncSetAttribute(attn_kernel,
                         cudaFuncAttributeMaxDynamicSharedMemorySize, ATTN_SMEM);
    cudaFuncSetAttribute(gemm_mma<0>,
                         cudaFuncAttributeMaxDynamicSharedMemorySize, GEMM_SMEM);
    cudaFuncSetAttribute(gemm_mma<2>,
                         cudaFuncAttributeMaxDynamicSharedMemorySize, GEMM_SMEM);
    cudaFuncSetAttribute(gemm_mma64<1>,
                         cudaFuncAttributeMaxDynamicSharedMemorySize, GEMM_SMEM64);

    // 0. round all weights to tf32 (RN) in one launch
    round_all_kernel<<<(NTOT4 + 255) / 256, 256>>>(
        qkv_w, p_wq, proj_w, p_wp, fc1_w, p_w1, fc2_w, p_w2);

    // 1. norm1
    ln_split_kernel<<<TOK, 128>>>(x, ln1a_g, ln1a_b, ln1b_g, ln1b_b,
                                  ln1c_g, ln1c_b, p_normx);

    // 2. QKV (128x128 tiles: 1152 CTAs, good wave fill)
    gemm_mma<0><<<dim3(3 * DIM / 128, TOK / 128), 128, GEMM_SMEM>>>(
        p_normx, p_wq, nullptr, nullptr, p_qkv, TOK, 3 * DIM, DIM);

    // 3. attention
    attn_kernel<<<dim3(SEQ / 64, BATCH * NHEAD), 128, ATTN_SMEM>>>(p_qkv, p_y);

    // 4. proj + bias + residual(x) — 64x128 tiles (768 CTAs, wave fix)
    gemm_mma64<1><<<dim3(DIM / 128, TOK / 64), 128, GEMM_SMEM64>>>(
        p_y, p_wp, proj_b, x, out, TOK, DIM, DIM);

    // 5. norm2
    ln_split_kernel<<<TOK, 128>>>(out, ln2a_g, ln2a_b, ln2b_g, ln2b_b,
                                  ln2c_g, ln2c_b, p_normx);

    // 6. FC1 + bias + GELU (128x128 tiles)
    gemm_mma<2><<<dim3(HID / 128, TOK / 128), 128, GEMM_SMEM>>>(
        p_normx, p_w1, fc1_b, nullptr, p_h, TOK, HID, DIM);

    // 7. FC2 + bias + residual(out) — 64x128 tiles (wave fix)
    gemm_mma64<1><<<dim3(DIM / 128, TOK / 64), 128, GEMM_SMEM64>>>(
        p_h, p_w2, fc2_b, out, out, TOK, DIM, HID);
}

// round 17
// speedup vs baseline: 1.0569x; 1.0057x over previous
#include <cuda_runtime.h>
#include <math.h>
#include <stdint.h>
#include <mma.h>

using namespace nvcuda;

// ---------------------------------------------------------------------------
// Problem constants
// ---------------------------------------------------------------------------
#define DIM   768
#define NHEAD 12
#define HD    64
#define BATCH 8
#define SEQ   1024
#define TOK   (BATCH*SEQ)
#define HID   3072
#define S1V   320
#define S2V   384
#define EPS   1e-5f
#define SCALE 0.125f

// ---------------------------------------------------------------------------
// Scratch
// ---------------------------------------------------------------------------
__device__ float g_normx[TOK * DIM];
__device__ float g_qkv  [TOK * 3 * DIM];
__device__ float g_y    [TOK * DIM];
__device__ float g_h    [TOK * HID];
__device__ float g_wq[3 * DIM * DIM];
__device__ float g_wp[DIM * DIM];
__device__ float g_w1[HID * DIM];
__device__ float g_w2[DIM * HID];

// ---------------------------------------------------------------------------
// Fused weight rounding
// ---------------------------------------------------------------------------
#define NQ4 (3 * DIM * DIM / 4)
#define NP4 (DIM * DIM / 4)
#define N14 (HID * DIM / 4)
#define N24 (DIM * HID / 4)
#define NTOT4 (NQ4 + NP4 + N14 + N24)

__global__ void __launch_bounds__(256) round_all_kernel(
    const float* __restrict__ sq, float* __restrict__ dq,
    const float* __restrict__ sp, float* __restrict__ dp,
    const float* __restrict__ s1, float* __restrict__ d1,
    const float* __restrict__ s2, float* __restrict__ d2)
{
    int i = blockIdx.x * 256 + threadIdx.x;
    if (i >= NTOT4) return;
    const float4* src;
    float4* dst;
    int off;
    if (i < NQ4)                  { src = (const float4*)sq; dst = (float4*)dq; off = i; }
    else if (i < NQ4 + NP4)       { src = (const float4*)sp; dst = (float4*)dp; off = i - NQ4; }
    else if (i < NQ4 + NP4 + N14) { src = (const float4*)s1; dst = (float4*)d1; off = i - NQ4 - NP4; }
    else                          { src = (const float4*)s2; dst = (float4*)d2; off = i - NQ4 - NP4 - N14; }
    float4 v = src[off];
    v.x = wmma::__float_to_tf32(v.x);
    v.y = wmma::__float_to_tf32(v.y);
    v.z = wmma::__float_to_tf32(v.z);
    v.w = wmma::__float_to_tf32(v.w);
    dst[off] = v;
}

// ---------------------------------------------------------------------------
// PTX helpers
// ---------------------------------------------------------------------------
__device__ __forceinline__ void cp_async16(uint32_t dst, const float* src) {
    asm volatile("cp.async.cg.shared.global [%0], [%1], 16;\n"
                 :: "r"(dst), "l"(src));
}
__device__ __forceinline__ void cp_commit() {
    asm volatile("cp.async.commit_group;\n" ::: "memory");
}
__device__ __forceinline__ void cp_wait1() {
    asm volatile("cp.async.wait_group 1;\n" ::: "memory");
}
__device__ __forceinline__ void ldsm4(uint32_t& r0, uint32_t& r1,
                                      uint32_t& r2, uint32_t& r3, uint32_t addr) {
    asm volatile("ldmatrix.sync.aligned.m8n8.x4.shared.b16 {%0,%1,%2,%3}, [%4];"
                 : "=r"(r0), "=r"(r1), "=r"(r2), "=r"(r3) : "r"(addr));
}
__device__ __forceinline__ void mma8(float* d,
    uint32_t a0, uint32_t a1, uint32_t a2, uint32_t a3,
    uint32_t b0, uint32_t b1)
{
    asm volatile(
        "mma.sync.aligned.m16n8k8.row.col.f32.tf32.tf32.f32 "
        "{%0,%1,%2,%3},{%4,%5,%6,%7},{%8,%9},{%0,%1,%2,%3};"
        : "+f"(d[0]), "+f"(d[1]), "+f"(d[2]), "+f"(d[3])
        : "r"(a0), "r"(a1), "r"(a2), "r"(a3), "r"(b0), "r"(b1));
}

__device__ __forceinline__ float gelu_tf32(float x) {
    return wmma::__float_to_tf32(0.5f * x * (1.0f + erff(x * 0.70710678118654752f)));
}

// ---------------------------------------------------------------------------
// Raw-mma TF32 NT GEMM, CTA 128x128 (proven R12 config) — QKV.
// ---------------------------------------------------------------------------
#define LDA 36
#define STAGE_F (128 * LDA)
#define GEMM_SMEM (3 * 2 * STAGE_F * 4)

template<int EPI>
__global__ void __launch_bounds__(128, 2) gemm_mma(
    const float* __restrict__ A, const float* __restrict__ B,
    const float* __restrict__ bias, const float* __restrict__ res,
    float* __restrict__ C, int M, int N, int K)
{
    extern __shared__ float smem[];

    const int tid  = threadIdx.x;
    const int w    = tid >> 5;
    const int lane = tid & 31;
    const int bm = blockIdx.y, bn = blockIdx.x;
    const int wm = w & 1;
    const int wn = w >> 1;

    const float* Abase = A + (size_t)(bm * 128) * K;
    const float* Bbase = B + (size_t)(bn * 128) * K;

    const uint32_t smem_u32 = (uint32_t)__cvta_generic_to_shared(smem);

    const int arow_l = lane & 15;
    const int acol_l = (lane >> 4) << 2;
    const int brow_l = (lane & 7) + ((lane >> 4) << 3);
    const int bcol_l = ((lane >> 3) & 1) << 2;

    float acc[4][8][4];
#pragma unroll
    for (int i = 0; i < 4; i++)
#pragma unroll
        for (int j = 0; j < 8; j++)
#pragma unroll
            for (int e = 0; e < 4; e++) acc[i][j][e] = 0.f;

    const int KC = K >> 5;

    auto issue = [&](int c, int s) {
        const int k0 = c << 5;
        const uint32_t sbase = smem_u32 + (uint32_t)(s * 2 * STAGE_F) * 4u;
#pragma unroll
        for (int i = 0; i < 8; i++) {
            int idx = tid + i * 128, r = idx >> 3, cc = idx & 7;
            cp_async16(sbase + (uint32_t)(r * LDA + cc * 4) * 4u,
                       Abase + (size_t)r * K + k0 + cc * 4);
        }
#pragma unroll
        for (int i = 0; i < 8; i++) {
            int idx = tid + i * 128, r = idx >> 3, cc = idx & 7;
            cp_async16(sbase + (uint32_t)(STAGE_F + r * LDA + cc * 4) * 4u,
                       Bbase + (size_t)r * K + k0 + cc * 4);
        }
    };

    issue(0, 0); cp_commit();
    issue(1, 1); cp_commit();

    int s3 = 2;
    for (int c = 0; c < KC; c++) {
        cp_wait1();
        __syncthreads();
        if (c + 2 < KC) issue(c + 2, s3);
        cp_commit();
        s3 = (s3 == 2) ? 0 : s3 + 1;

        const uint32_t soff = (uint32_t)((c % 3) * 2 * STAGE_F) * 4u;
        const uint32_t abase = smem_u32 + soff +
            (uint32_t)((wm * 64 + arow_l) * LDA + acol_l) * 4u;
        const uint32_t bbase = smem_u32 + soff + (uint32_t)STAGE_F * 4u +
            (uint32_t)((wn * 64 + brow_l) * LDA + bcol_l) * 4u;

#pragma unroll
        for (int kk = 0; kk < 32; kk += 8) {
            uint32_t a[4][4], b[4][4];
#pragma unroll
            for (int i = 0; i < 4; i++)
                ldsm4(a[i][0], a[i][1], a[i][2], a[i][3],
                      abase + (uint32_t)(i * 16 * LDA + kk) * 4u);
#pragma unroll
            for (int j = 0; j < 4; j++)
                ldsm4(b[j][0], b[j][1], b[j][2], b[j][3],
                      bbase + (uint32_t)(j * 16 * LDA + kk) * 4u);
#pragma unroll
            for (int i = 0; i < 4; i++)
#pragma unroll
                for (int j = 0; j < 4; j++) {
                    mma8(acc[i][2 * j],     a[i][0], a[i][1], a[i][2], a[i][3],
                         b[j][0], b[j][1]);
                    mma8(acc[i][2 * j + 1], a[i][0], a[i][1], a[i][2], a[i][3],
                         b[j][2], b[j][3]);
                }
        }
    }

    const int gr0 = bm * 128 + wm * 64 + (lane >> 2);
    const int gc0 = bn * 128 + wn * 64 + 2 * (lane & 3);

#pragma unroll
    for (int i = 0; i < 4; i++) {
        const int r0 = gr0 + i * 16;
        const int r1 = r0 + 8;
#pragma unroll
        for (int jj = 0; jj < 8; jj++) {
            const int col = gc0 + jj * 8;
            float* d = acc[i][jj];
            float v0 = d[0], v1 = d[1], v2 = d[2], v3 = d[3];
            if (EPI == 1) {
                float b0 = bias[col], b1 = bias[col + 1];
                const float* rr0 = res + (size_t)r0 * N + col;
                const float* rr1 = res + (size_t)r1 * N + col;
                v0 += b0 + rr0[0]; v1 += b1 + rr0[1];
                v2 += b0 + rr1[0]; v3 += b1 + rr1[1];
            } else if (EPI == 2) {
                float b0 = bias[col], b1 = bias[col + 1];
                v0 = gelu_tf32(v0 + b0); v1 = gelu_tf32(v1 + b1);
                v2 = gelu_tf32(v2 + b0); v3 = gelu_tf32(v3 + b1);
            }
            *(float2*)(C + (size_t)r0 * N + col) = make_float2(v0, v1);
            *(float2*)(C + (size_t)r1 * N + col) = make_float2(v2, v3);
        }
    }
}

// ---------------------------------------------------------------------------
// Raw-mma TF32 NT GEMM, CTA 64x128 — proj / FC1 / FC2 (wave-quantization fix).
// ---------------------------------------------------------------------------
#define STAGE_A64 (64 * LDA)
#define STAGE_T64 (STAGE_A64 + 128 * LDA)
#define GEMM_SMEM64 (3 * STAGE_T64 * 4)

template<int EPI>
__global__ void __launch_bounds__(128, 2) gemm_mma64(
    const float* __restrict__ A, const float* __restrict__ B,
    const float* __restrict__ bias, const float* __restrict__ res,
    float* __restrict__ C, int M, int N, int K)
{
    extern __shared__ float smem[];

    const int tid  = threadIdx.x;
    const int w    = tid >> 5;
    const int lane = tid & 31;
    const int bm = blockIdx.y, bn = blockIdx.x;
    const int wm = w & 1;       // 2 m-slices of 32
    const int wn = w >> 1;      // 2 n-slices of 64

    const float* Abase = A + (size_t)(bm * 64) * K;
    const float* Bbase = B + (size_t)(bn * 128) * K;

    const uint32_t smem_u32 = (uint32_t)__cvta_generic_to_shared(smem);

    const int arow_l = lane & 15;
    const int acol_l = (lane >> 4) << 2;
    const int brow_l = (lane & 7) + ((lane >> 4) << 3);
    const int bcol_l = ((lane >> 3) & 1) << 2;

    float acc[2][8][4];
#pragma unroll
    for (int i = 0; i < 2; i++)
#pragma unroll
        for (int j = 0; j < 8; j++)
#pragma unroll
            for (int e = 0; e < 4; e++) acc[i][j][e] = 0.f;

    const int KC = K >> 5;

    auto issue = [&](int c, int s) {
        const int k0 = c << 5;
        const uint32_t sbase = smem_u32 + (uint32_t)(s * STAGE_T64) * 4u;
#pragma unroll
        for (int i = 0; i < 4; i++) {
            int idx = tid + i * 128, r = idx >> 3, cc = idx & 7;
            cp_async16(sbase + (uint32_t)(r * LDA + cc * 4) * 4u,
                       Abase + (size_t)r * K + k0 + cc * 4);
        }
#pragma unroll
        for (int i = 0; i < 8; i++) {
            int idx = tid + i * 128, r = idx >> 3, cc = idx & 7;
            cp_async16(sbase + (uint32_t)(STAGE_A64 + r * LDA + cc * 4) * 4u,
                       Bbase + (size_t)r * K + k0 + cc * 4);
        }
    };

    issue(0, 0); cp_commit();
    issue(1, 1); cp_commit();

    int s3 = 2;
    for (int c = 0; c < KC; c++) {
        cp_wait1();
        __syncthreads();
        if (c + 2 < KC) issue(c + 2, s3);
        cp_commit();
        s3 = (s3 == 2) ? 0 : s3 + 1;

        const uint32_t soff = (uint32_t)((c % 3) * STAGE_T64) * 4u;
        const uint32_t abase = smem_u32 + soff +
            (uint32_t)((wm * 32 + arow_l) * LDA + acol_l) * 4u;
        const uint32_t bbase = smem_u32 + soff + (uint32_t)STAGE_A64 * 4u +
            (uint32_t)((wn * 64 + brow_l) * LDA + bcol_l) * 4u;

#pragma unroll
        for (int kk = 0; kk < 32; kk += 8) {
            uint32_t a[2][4], b[4][4];
#pragma unroll
            for (int i = 0; i < 2; i++)
                ldsm4(a[i][0], a[i][1], a[i][2], a[i][3],
                      abase + (uint32_t)(i * 16 * LDA + kk) * 4u);
#pragma unroll
            for (int j = 0; j < 4; j++)
                ldsm4(b[j][0], b[j][1], b[j][2], b[j][3],
                      bbase + (uint32_t)(j * 16 * LDA + kk) * 4u);
#pragma unroll
            for (int i = 0; i < 2; i++)
#pragma unroll
                for (int j = 0; j < 4; j++) {
                    mma8(acc[i][2 * j],     a[i][0], a[i][1], a[i][2], a[i][3],
                         b[j][0], b[j][1]);
                    mma8(acc[i][2 * j + 1], a[i][0], a[i][1], a[i][2], a[i][3],
                         b[j][2], b[j][3]);
                }
        }
    }

    const int gr0 = bm * 64 + wm * 32 + (lane >> 2);
    const int gc0 = bn * 128 + wn * 64 + 2 * (lane & 3);

#pragma unroll
    for (int i = 0; i < 2; i++) {
        const int r0 = gr0 + i * 16;
        const int r1 = r0 + 8;
#pragma unroll
        for (int jj = 0; jj < 8; jj++) {
            const int col = gc0 + jj * 8;
            float* d = acc[i][jj];
            float v0 = d[0], v1 = d[1], v2 = d[2], v3 = d[3];
            if (EPI == 1) {
                float b0 = bias[col], b1 = bias[col + 1];
                const float* rr0 = res + (size_t)r0 * N + col;
                const float* rr1 = res + (size_t)r1 * N + col;
                v0 += b0 + rr0[0]; v1 += b1 + rr0[1];
                v2 += b0 + rr1[0]; v3 += b1 + rr1[1];
            } else if (EPI == 2) {
                float b0 = bias[col], b1 = bias[col + 1];
                v0 = gelu_tf32(v0 + b0); v1 = gelu_tf32(v1 + b1);
                v2 = gelu_tf32(v2 + b0); v3 = gelu_tf32(v3 + b1);
            }
            *(float2*)(C + (size_t)r0 * N + col) = make_float2(v0, v1);
            *(float2*)(C + (size_t)r1 * N + col) = make_float2(v2, v3);
        }
    }
}

// ---------------------------------------------------------------------------
// Split LayerNorm (unchanged)
// ---------------------------------------------------------------------------
__global__ void __launch_bounds__(128) ln_split_kernel(
    const float* __restrict__ x,
    const float* __restrict__ ga, const float* __restrict__ ba,
    const float* __restrict__ gb, const float* __restrict__ bb,
    const float* __restrict__ gc, const float* __restrict__ bc,
    float* __restrict__ out)
{
    __shared__ float xs[DIM];
    __shared__ float st_m[3];
    __shared__ float st_r[3];

    const int row = blockIdx.x;
    const int tid = threadIdx.x;
    const int w = tid >> 5, lane = tid & 31;

    const float4* xr4 = (const float4*)(x + (size_t)row * DIM);
    float4* xs4 = (float4*)xs;
    xs4[tid] = xr4[tid];
    if (tid < 64) xs4[128 + tid] = xr4[128 + tid];
    __syncthreads();

    if (w < 3) {
        const int lo  = (w == 0) ? 0 : ((w == 1) ? S1V : S2V);
        const int hi  = (w == 0) ? S1V : ((w == 1) ? S2V : DIM);
        float s1 = 0.f, s2 = 0.f;
        for (int i = lo + lane; i < hi; i += 32) {
            float v = xs[i];
            s1 += v; s2 += v * v;
        }
#pragma unroll
        for (int off = 16; off > 0; off >>= 1) {
            s1 += __shfl_xor_sync(0xffffffffu, s1, off);
            s2 += __shfl_xor_sync(0xffffffffu, s2, off);
        }
        if (lane == 0) {
            float len = (float)(hi - lo);
            float m = s1 / len;
            float var = s2 / len - m * m;
            st_m[w] = m;
            st_r[w] = rsqrtf(var + EPS);
        }
    }
    __syncthreads();

    float* orow = out + (size_t)row * DIM;
    for (int i = tid; i < DIM; i += 128) {
        int s = (i < S1V) ? 0 : ((i < S2V) ? 1 : 2);
        int li = i - ((s == 0) ? 0 : ((s == 1) ? S1V : S2V));
        const float* g  = (s == 0) ? ga : ((s == 1) ? gb : gc);
        const float* be = (s == 0) ? ba : ((s == 1) ? bb : bc);
        float v = (xs[i] - st_m[s]) * st_r[s] * g[li] + be[li];
        orow[i] = wmma::__float_to_tf32(v);
    }
}

// ---------------------------------------------------------------------------
// Tensor-core flash attention — R12 scalar version (proven 252us, unchanged).
// ---------------------------------------------------------------------------
#define ALDK 68
#define ALDV 72
#define ATTN_SMEM ((2 * 64 * ALDK + 64 * ALDV) * 4)

__global__ void __launch_bounds__(128) attn_kernel(
    const float* __restrict__ qkv, float* __restrict__ y)
{
    extern __shared__ float sm[];
    float* qs = sm;
    float* ks = sm + 64 * ALDK;
    float* vs = sm + 2 * 64 * ALDK;

    const int tid  = threadIdx.x;
    const int w    = tid >> 5;
    const int lane = tid & 31;
    const int qr   = lane >> 2;
    const int qc   = lane & 3;
    const int n0 = blockIdx.x * 64;
    const int b = blockIdx.y / NHEAD;
    const int h = blockIdx.y % NHEAD;

    const float* base = qkv + (size_t)b * SEQ * (3 * DIM) + h * HD;

    for (int i = tid; i < 64 * 16; i += 128) {
        int r = i >> 4, c4 = (i & 15) * 4;
        *(float4*)(qs + r * ALDK + c4) =
            *(const float4*)(base + (size_t)(n0 + r) * (3 * DIM) + c4);
    }

    float o[8][4];
    float m0 = -INFINITY, m1 = -INFINITY, l0 = 0.f, l1 = 0.f;
#pragma unroll
    for (int j = 0; j < 8; j++)
#pragma unroll
        for (int e = 0; e < 4; e++) o[j][e] = 0.f;

    const int rowA = (w * 16 + qr) * ALDK;
    const int rowB = rowA + 8 * ALDK;

    for (int kt = 0; kt < SEQ / 64; kt++) {
        for (int i = tid; i < 64 * 16; i += 128) {
            int r = i >> 4, c4 = (i & 15) * 4;
            const float* kp = base + DIM + (size_t)(kt * 64 + r) * (3 * DIM) + c4;
            *(float4*)(ks + r * ALDK + c4) = *(const float4*)kp;
            *(float4*)(vs + r * ALDV + c4) = *(const float4*)(kp + DIM);
        }
        __syncthreads();

        float s[8][4];
#pragma unroll
        for (int j = 0; j < 8; j++)
#pragma unroll
            for (int e = 0; e < 4; e++) s[j][e] = 0.f;

#pragma unroll
        for (int k8 = 0; k8 < 8; k8++) {
            const int kb = k8 * 8;
            uint32_t a0 = __float_as_uint(qs[rowA + kb + qc]);
            uint32_t a1 = __float_as_uint(qs[rowB + kb + qc]);
            uint32_t a2 = __float_as_uint(qs[rowA + kb + qc + 4]);
            uint32_t a3 = __float_as_uint(qs[rowB + kb + qc + 4]);
#pragma unroll
            for (int j = 0; j < 8; j++) {
                uint32_t b0 = __float_as_uint(ks[(j * 8 + qr) * ALDK + kb + qc]);
                uint32_t b1 = __float_as_uint(ks[(j * 8 + qr) * ALDK + kb + qc + 4]);
                mma8(s[j], a0, a1, a2, a3, b0, b1);
            }
        }
        __syncthreads();

        float mx0 = -INFINITY, mx1 = -INFINITY;
#pragma unroll
        for (int j = 0; j < 8; j++) {
#pragma unroll
            for (int e = 0; e < 4; e++) s[j][e] *= SCALE;
            mx0 = fmaxf(mx0, fmaxf(s[j][0], s[j][1]));
            mx1 = fmaxf(mx1, fmaxf(s[j][2], s[j][3]));
        }
        mx0 = fmaxf(mx0, __shfl_xor_sync(0xffffffffu, mx0, 1));
        mx0 = fmaxf(mx0, __shfl_xor_sync(0xffffffffu, mx0, 2));
        mx1 = fmaxf(mx1, __shfl_xor_sync(0xffffffffu, mx1, 1));
        mx1 = fmaxf(mx1, __shfl_xor_sync(0xffffffffu, mx1, 2));

        float mn0 = fmaxf(m0, mx0), mn1 = fmaxf(m1, mx1);
        float c0 = __expf(m0 - mn0), c1 = __expf(m1 - mn1);
        float rs0 = 0.f, rs1 = 0.f;

#pragma unroll
        for (int j = 0; j < 8; j++) {
            float p0 = __expf(s[j][0] - mn0);
            float p1 = __expf(s[j][1] - mn0);
            float p2 = __expf(s[j][2] - mn1);
            float p3 = __expf(s[j][3] - mn1);
            rs0 += p0 + p1; rs1 += p2 + p3;
            float* pr0 = ks + rowA + j * 8 + qc * 2;
            float* pr1 = ks + rowB + j * 8 + qc * 2;
            pr0[0] = p0; pr0[1] = p1;
            pr1[0] = p2; pr1[1] = p3;
            o[j][0] *= c0; o[j][1] *= c0; o[j][2] *= c1; o[j][3] *= c1;
        }
        rs0 += __shfl_xor_sync(0xffffffffu, rs0, 1);
        rs0 += __shfl_xor_sync(0xffffffffu, rs0, 2);
        rs1 += __shfl_xor_sync(0xffffffffu, rs1, 1);
        rs1 += __shfl_xor_sync(0xffffffffu, rs1, 2);
        l0 = l0 * c0 + rs0; l1 = l1 * c1 + rs1;
        m0 = mn0; m1 = mn1;
        __syncwarp();

#pragma unroll
        for (int k8 = 0; k8 < 8; k8++) {
            const int kb = k8 * 8;
            uint32_t a0 = __float_as_uint(ks[rowA + kb + qc]);
            uint32_t a1 = __float_as_uint(ks[rowB + kb + qc]);
            uint32_t a2 = __float_as_uint(ks[rowA + kb + qc + 4]);
            uint32_t a3 = __float_as_uint(ks[rowB + kb + qc + 4]);
#pragma unroll
            for (int j = 0; j < 8; j++) {
                uint32_t b0 = __float_as_uint(vs[(kb + qc) * ALDV + j * 8 + qr]);
                uint32_t b1 = __float_as_uint(vs[(kb + qc + 4) * ALDV + j * 8 + qr]);
                mma8(o[j], a0, a1, a2, a3, b0, b1);
            }
        }
        __syncthreads();
    }

    const float i0 = 1.0f / l0, i1 = 1.0f / l1;
    const int gr0 = b * SEQ + n0 + w * 16 + qr;
    float* y0 = y + (size_t)gr0 * DIM + h * HD;
    float* y1 = y0 + (size_t)8 * DIM;
#pragma unroll
    for (int j = 0; j < 8; j++) {
        const int cb = j * 8 + qc * 2;
        y0[cb]     = wmma::__float_to_tf32(o[j][0] * i0);
        y0[cb + 1] = wmma::__float_to_tf32(o[j][1] * i0);
        y1[cb]     = wmma::__float_to_tf32(o[j][2] * i1);
        y1[cb + 1] = wmma::__float_to_tf32(o[j][3] * i1);
    }
}

// ---------------------------------------------------------------------------
// Launch
// ---------------------------------------------------------------------------
extern "C" void kernel_launch(void* const* d_in, const int* in_sizes, int n_in,
                              void* d_out, int out_size)
{
    const float* x      = (const float*)d_in[0];
    const float* ln1a_g = (const float*)d_in[1];
    const float* ln1a_b = (const float*)d_in[2];
    const float* ln1b_g = (const float*)d_in[3];
    const float* ln1b_b = (const float*)d_in[4];
    const float* ln1c_g = (const float*)d_in[5];
    const float* ln1c_b = (const float*)d_in[6];
    const float* ln2a_g = (const float*)d_in[7];
    const float* ln2a_b = (const float*)d_in[8];
    const float* ln2b_g = (const float*)d_in[9];
    const float* ln2b_b = (const float*)d_in[10];
    const float* ln2c_g = (const float*)d_in[11];
    const float* ln2c_b = (const float*)d_in[12];
    const float* qkv_w  = (const float*)d_in[13];
    const float* proj_w = (const float*)d_in[14];
    const float* proj_b = (const float*)d_in[15];
    const float* fc1_w  = (const float*)d_in[16];
    const float* fc1_b  = (const float*)d_in[17];
    const float* fc2_w  = (const float*)d_in[18];
    const float* fc2_b  = (const float*)d_in[19];
    float* out = (float*)d_out;

    float *p_normx, *p_qkv, *p_y, *p_h, *p_wq, *p_wp, *p_w1, *p_w2;
    cudaGetSymbolAddress((void**)&p_normx, g_normx);
    cudaGetSymbolAddress((void**)&p_qkv,   g_qkv);
    cudaGetSymbolAddress((void**)&p_y,     g_y);
    cudaGetSymbolAddress((void**)&p_h,     g_h);
    cudaGetSymbolAddress((void**)&p_wq,    g_wq);
    cudaGetSymbolAddress((void**)&p_wp,    g_wp);
    cudaGetSymbolAddress((void**)&p_w1,    g_w1);
    cudaGetSymbolAddress((void**)&p_w2,    g_w2);

    cudaFuncSetAttribute(attn_kernel,
                         cudaFuncAttributeMaxDynamicSharedMemorySize, ATTN_SMEM);
    cudaFuncSetAttribute(gemm_mma<0>,
                         cudaFuncAttributeMaxDynamicSharedMemorySize, GEMM_SMEM);
    cudaFuncSetAttribute(gemm_mma64<1>,
                         cudaFuncAttributeMaxDynamicSharedMemorySize, GEMM_SMEM64);
    cudaFuncSetAttribute(gemm_mma64<2>,
                         cudaFuncAttributeMaxDynamicSharedMemorySize, GEMM_SMEM64);

    // 0. round all weights to tf32 (RN) in one launch
    round_all_kernel<<<(NTOT4 + 255) / 256, 256>>>(
        qkv_w, p_wq, proj_w, p_wp, fc1_w, p_w1, fc2_w, p_w2);

    // 1. norm1
    ln_split_kernel<<<TOK, 128>>>(x, ln1a_g, ln1a_b, ln1b_g, ln1b_b,
                                  ln1c_g, ln1c_b, p_normx);

    // 2. QKV (128x128 tiles: 1152 CTAs, 97% wave fill)
    gemm_mma<0><<<dim3(3 * DIM / 128, TOK / 128), 128, GEMM_SMEM>>>(
        p_normx, p_wq, nullptr, nullptr, p_qkv, TOK, 3 * DIM, DIM);

    // 3. attention
    attn_kernel<<<dim3(SEQ / 64, BATCH * NHEAD), 128, ATTN_SMEM>>>(p_qkv, p_y);

    // 4. proj + bias + residual(x) — 64x128 tiles
    gemm_mma64<1><<<dim3(DIM / 128, TOK / 64), 128, GEMM_SMEM64>>>(
        p_y, p_wp, proj_b, x, out, TOK, DIM, DIM);

    // 5. norm2
    ln_split_kernel<<<TOK, 128>>>(out, ln2a_g, ln2a_b, ln2b_g, ln2b_b,
                                  ln2c_g, ln2c_b, p_normx);

    // 6. FC1 + bias + GELU — 64x128 tiles (wave fix: 3072 CTAs, 94% fill)
    gemm_mma64<2><<<dim3(HID / 128, TOK / 64), 128, GEMM_SMEM64>>>(
        p_normx, p_w1, fc1_b, nullptr, p_h, TOK, HID, DIM);

    // 7. FC2 + bias + residual(out) — 64x128 tiles
    gemm_mma64<1><<<dim3(DIM / 128, TOK / 64), 128, GEMM_SMEM64>>>(
        p_h, p_w2, fc2_b, out, out, TOK, DIM, HID);
}